// round 12
// baseline (speedup 1.0000x reference)
#include <cuda_runtime.h>
#include <cuda_fp16.h>
#include <cstdint>

// ---------------------------------------------------------------------------
// GraphSAGE with sampling, GB300 (compute_103 virtual arch -> no tcgen05).
// Round 12:
//  - gather split into dedicated k_agg<L> kernels (high occupancy, 16 loads
//    in flight per warp) writing g_agg fp16
//  - k_conv_mma: pure streaming GEMM, W + Wagg fully smem-resident, 1 sync
//  - h0 / prep unchanged (h0 is at its memory roofline)
// Env constraint: dynamic smem <= ~116 KB per CTA (conv uses 102,400 B).
// ---------------------------------------------------------------------------

#define FEATC 128
#define CONTC 256
#define S2C   8192
#define S1C   73728        /* S2*9 */
#define S0C   663552       /* S1*9 */

// weight pool offsets (elements)
#define OFF_WP    0
#define OFF_W0    32768
#define OFF_WAGG0 65536
#define OFF_W1    81920
#define OFF_WAGG1 114688
#define W_TOTAL   131072

__device__ __half g_h0h[(long long)S0C * FEATC];   // 169.9 MB scratch
__device__ __half g_h1h[(long long)S1C * FEATC];   // 18.9 MB scratch
__device__ __half g_agg[(long long)S1C * FEATC];   // 18.9 MB scratch
__device__ __half g_w16[W_TOTAL];                  // fp16 weights (all 5)

static __device__ __forceinline__ float leaky01(float x) {
    return x < 0.0f ? 0.1f * x : x;
}
static __device__ __forceinline__ uint32_t h2u(__half2 h) {
    return *reinterpret_cast<uint32_t*>(&h);
}

// mma.sync m16n8k16 row.col f32.f16.f16.f32, accumulate in place
static __device__ __forceinline__ void mma16816h(
    float* c, const uint32_t* a, const uint32_t* b)
{
    asm volatile(
        "mma.sync.aligned.m16n8k16.row.col.f32.f16.f16.f32 "
        "{%0,%1,%2,%3}, {%4,%5,%6,%7}, {%8,%9}, {%0,%1,%2,%3};"
        : "+f"(c[0]), "+f"(c[1]), "+f"(c[2]), "+f"(c[3])
        : "r"(a[0]), "r"(a[1]), "r"(a[2]), "r"(a[3]),
          "r"(b[0]), "r"(b[1]));
}

// ---------------------------------------------------------------------------
// k_prep: fp16 conversion of all weight matrices.
// ---------------------------------------------------------------------------
__global__ void k_prep(const float* __restrict__ Wp, const float* __restrict__ W0,
                       const float* __restrict__ Wagg0, const float* __restrict__ W1,
                       const float* __restrict__ Wagg1)
{
    int i = blockIdx.x * blockDim.x + threadIdx.x;
    if (i >= W_TOTAL) return;
    float v;
    if      (i < OFF_W0)    v = Wp[i - OFF_WP];
    else if (i < OFF_WAGG0) v = W0[i - OFF_W0];
    else if (i < OFF_W1)    v = Wagg0[i - OFF_WAGG0];
    else if (i < OFF_WAGG1) v = W1[i - OFF_W1];
    else                    v = Wagg1[i - OFF_WAGG1];
    g_w16[i] = __float2half_rn(v);
}

// ---------------------------------------------------------------------------
// k_h0_mma: fp16 GEMM, CTA 128x128, whole Wp in smem, one sync. (unchanged)
// ---------------------------------------------------------------------------
#define WPITCH 264
#define H0_SMEM_BYTES (128 * WPITCH * 2)   /* 67,584 B */

__global__ __launch_bounds__(256, 2) void k_h0_mma(
    const float* __restrict__ content,   // [S0,256]
    const float* __restrict__ bp,        // [128]
    const float* __restrict__ node_emb,  // [N+1,128]
    const int*   __restrict__ parent)    // [S0]
{
    extern __shared__ __half Ws[];       // [128][WPITCH]

    const int tid  = threadIdx.x;
    const int lane = tid & 31;
    const int warp = tid >> 5;
    const int gID  = lane >> 2;
    const int qid  = lane & 3;
    const long long m0 = (long long)blockIdx.x * 128;
    const int mbase = warp * 16;

#pragma unroll
    for (int it = 0; it < 16; it++) {
        int g = tid + 256 * it;
        int n = g >> 5;
        int c = (g & 31) * 8;
        *(uint4*)&Ws[n * WPITCH + c] = *(const uint4*)(g_w16 + OFF_WP + n * CONTC + c);
    }

    float acc[16][4];
#pragma unroll
    for (int nj = 0; nj < 16; nj++)
#pragma unroll
        for (int t = 0; t < 4; t++) acc[nj][t] = 0.0f;

    __syncthreads();

#pragma unroll
    for (int kc = 0; kc < 4; kc++) {
#pragma unroll
        for (int s = 0; s < 4; s++) {
            uint32_t a[4];
            const float* abase = content + (m0 + mbase + gID) * (long long)CONTC
                               + kc * 64 + s * 16 + qid * 2;
#pragma unroll
            for (int rr = 0; rr < 2; rr++)
#pragma unroll
                for (int kk = 0; kk < 2; kk++) {
                    float2 v = *(const float2*)(abase + rr * 8 * CONTC + kk * 8);
                    a[rr + kk * 2] = h2u(__float22half2_rn(v));
                }
            int cb = kc * 64 + s * 16 + qid * 2;
#pragma unroll
            for (int nj = 0; nj < 16; nj++) {
                int n = nj * 8 + gID;
                uint32_t b[2];
                b[0] = *(const uint32_t*)&Ws[n * WPITCH + cb];
                b[1] = *(const uint32_t*)&Ws[n * WPITCH + cb + 8];
                mma16816h(acc[nj], a, b);
            }
        }
    }

#pragma unroll
    for (int rr = 0; rr < 2; rr++) {
        long long r = m0 + mbase + rr * 8 + gID;
        long long p = (long long)parent[r] + 1;
        const float* ne = node_emb + p * FEATC;
        __half* orow = g_h0h + r * FEATC;
#pragma unroll
        for (int nj = 0; nj < 16; nj++) {
            int c = nj * 8 + qid * 2;
            float2 bv = *(const float2*)(bp + c);
            float2 nv = *(const float2*)(ne + c);
            float ox = leaky01(acc[nj][rr * 2 + 0] + bv.x) + nv.x;
            float oy = leaky01(acc[nj][rr * 2 + 1] + bv.y) + nv.y;
            *(__half2*)(orow + c) = __floats2half2_rn(ox, oy);
        }
    }
}

// ---------------------------------------------------------------------------
// k_agg<LAYER>: gather-mean of 8 random neighbors -> g_agg (fp16).
// 1 warp handles 2 consecutive rows (16 data loads in flight). Tiny smem,
// low regs -> high occupancy -> gather runs at random-access bandwidth.
// LAYER 1 adds the (h1[d] - h0[d]) self-edge correction.
// grid = n_rows/16, block = 256.
// ---------------------------------------------------------------------------
template <int LAYER>
__global__ __launch_bounds__(256) void k_agg(const int* __restrict__ nbr)
{
    const int tid  = threadIdx.x;
    const int lane = tid & 31;
    const int warp = tid >> 5;
    const long long row0 = (long long)blockIdx.x * 16 + warp * 2;
    const long long row1 = row0 + 1;
    const __half* hsrc = (LAYER == 0) ? g_h0h : g_h1h;

    int4 ea0 = *(const int4*)(nbr + row0 * 8);
    int4 eb0 = *(const int4*)(nbr + row0 * 8 + 4);
    int4 ea1 = *(const int4*)(nbr + row1 * 8);
    int4 eb1 = *(const int4*)(nbr + row1 * 8 + 4);
    int idx0[8] = {ea0.x, ea0.y, ea0.z, ea0.w, eb0.x, eb0.y, eb0.z, eb0.w};
    int idx1[8] = {ea1.x, ea1.y, ea1.z, ea1.w, eb1.x, eb1.y, eb1.z, eb1.w};

    uint2 u0[8], u1[8];
#pragma unroll
    for (int k = 0; k < 8; k++)
        u0[k] = *(const uint2*)(hsrc + (long long)idx0[k] * FEATC + lane * 4);
#pragma unroll
    for (int k = 0; k < 8; k++)
        u1[k] = *(const uint2*)(hsrc + (long long)idx1[k] * FEATC + lane * 4);

    float4 s0 = make_float4(0.f, 0.f, 0.f, 0.f);
    float4 s1 = make_float4(0.f, 0.f, 0.f, 0.f);
#pragma unroll
    for (int k = 0; k < 8; k++) {
        float2 f0 = __half22float2(*(__half2*)&u0[k].x);
        float2 f1 = __half22float2(*(__half2*)&u0[k].y);
        s0.x += f0.x; s0.y += f0.y; s0.z += f1.x; s0.w += f1.y;
        float2 g0 = __half22float2(*(__half2*)&u1[k].x);
        float2 g1 = __half22float2(*(__half2*)&u1[k].y);
        s1.x += g0.x; s1.y += g0.y; s1.z += g1.x; s1.w += g1.y;
    }
    if (LAYER == 1) {
        uint2 a1 = *(const uint2*)(g_h1h + row0 * FEATC + lane * 4);
        uint2 c1 = *(const uint2*)(g_h0h + row0 * FEATC + lane * 4);
        uint2 a2 = *(const uint2*)(g_h1h + row1 * FEATC + lane * 4);
        uint2 c2 = *(const uint2*)(g_h0h + row1 * FEATC + lane * 4);
        float2 p0 = __half22float2(*(__half2*)&a1.x), p1 = __half22float2(*(__half2*)&a1.y);
        float2 q0 = __half22float2(*(__half2*)&c1.x), q1 = __half22float2(*(__half2*)&c1.y);
        s0.x += p0.x - q0.x; s0.y += p0.y - q0.y;
        s0.z += p1.x - q1.x; s0.w += p1.y - q1.y;
        float2 r0 = __half22float2(*(__half2*)&a2.x), r1 = __half22float2(*(__half2*)&a2.y);
        float2 t0 = __half22float2(*(__half2*)&c2.x), t1 = __half22float2(*(__half2*)&c2.y);
        s1.x += r0.x - t0.x; s1.y += r0.y - t0.y;
        s1.z += r1.x - t1.x; s1.w += r1.y - t1.y;
    }
    s0.x *= 0.125f; s0.y *= 0.125f; s0.z *= 0.125f; s0.w *= 0.125f;
    s1.x *= 0.125f; s1.y *= 0.125f; s1.z *= 0.125f; s1.w *= 0.125f;
    uint2 o0, o1;
    *(__half2*)&o0.x = __floats2half2_rn(s0.x, s0.y);
    *(__half2*)&o0.y = __floats2half2_rn(s0.z, s0.w);
    *(__half2*)&o1.x = __floats2half2_rn(s1.x, s1.y);
    *(__half2*)&o1.y = __floats2half2_rn(s1.z, s1.w);
    *(uint2*)&g_agg[row0 * FEATC + lane * 4] = o0;
    *(uint2*)&g_agg[row1 * FEATC + lane * 4] = o1;
}

// ---------------------------------------------------------------------------
// k_conv_mma<LAYER>: pure streaming GEMM, 64 dst rows per CTA.
//  W [128x256] and Wagg [128x128] fully smem-resident; ONE pre-GEMM sync.
//  kc=0,1: acc1 += X(g_h0h) @ W[:,0:128].T
//  kc=2,3: acc1 += Agg(g_agg) @ W[:,128:256].T ; acc2 += Agg @ Wagg.T
// Dynamic smem (bytes), total 102,400:
//   [0, 67584)        Wsm  half[128][264]
//   [67584, +34816)   W2   half[128][136]   (red/scales overlay in epilogue)
// ---------------------------------------------------------------------------
#define W2PITCH 136
#define CONV_SMEM_BYTES (67584 + 34816)

template <int LAYER>
__global__ __launch_bounds__(256, 2) void k_conv_mma(
    const float* __restrict__ b,     // [128]
    const float* __restrict__ bagg,  // [128]
    float*       __restrict__ dout)  // layer1 output
{
    extern __shared__ char smem[];
    __half* Wsm = (__half*)smem;                     // [128][WPITCH]
    __half* W2  = (__half*)(smem + 67584);           // [128][W2PITCH]
    float* red    = (float*)(smem + 67584);          // [64][2], epilogue only
    float* scales = (float*)(smem + 67584 + 512);    // [64]

    const int tid  = threadIdx.x;
    const int lane = tid & 31;
    const int warp = tid >> 5;
    const int wm   = warp & 3;           // 16-row m-block
    const int wn   = warp >> 2;          // 64-col n-block
    const int gID  = lane >> 2;
    const int qid  = lane & 3;
    const long long m0 = (long long)blockIdx.x * 64;
    const int mbase = wm * 16;
    const int nbase = wn * 64;
    const int WOFF  = (LAYER == 0) ? OFF_W0 : OFF_W1;
    const int AOFF  = (LAYER == 0) ? OFF_WAGG0 : OFF_WAGG1;

    // ---- stage whole W [128x256] and whole Wagg [128x128] ----
#pragma unroll
    for (int it = 0; it < 16; it++) {
        int g = tid + 256 * it;
        int n = g >> 5;
        int c = (g & 31) * 8;
        *(uint4*)&Wsm[n * WPITCH + c] = *(const uint4*)(g_w16 + WOFF + n * CONTC + c);
    }
#pragma unroll
    for (int it = 0; it < 8; it++) {
        int g = tid + 256 * it;
        int n = g >> 4;
        int c = (g & 15) * 8;
        *(uint4*)&W2[n * W2PITCH + c] = *(const uint4*)(g_w16 + AOFF + n * FEATC + c);
    }

    float acc1[8][4], acc2[8][4];
#pragma unroll
    for (int nj = 0; nj < 8; nj++)
#pragma unroll
        for (int t = 0; t < 4; t++) { acc1[nj][t] = 0.f; acc2[nj][t] = 0.f; }

    __syncthreads();   // sync 1: weights staged

    // ---- kc = 0,1: acc1 += X @ W[:,0:128].T ----
#pragma unroll
    for (int kc = 0; kc < 2; kc++) {
#pragma unroll
        for (int s = 0; s < 4; s++) {
            uint32_t a[4];
            const __half* ab = g_h0h + (m0 + mbase + gID) * (long long)FEATC
                             + kc * 64 + s * 16 + qid * 2;
#pragma unroll
            for (int rr = 0; rr < 2; rr++)
#pragma unroll
                for (int kk = 0; kk < 2; kk++)
                    a[rr + kk * 2] = *(const uint32_t*)(ab + rr * 8 * FEATC + kk * 8);
            int cb = kc * 64 + s * 16 + qid * 2;
#pragma unroll
            for (int nj = 0; nj < 8; nj++) {
                int n = nbase + nj * 8 + gID;
                uint32_t bb[2];
                bb[0] = *(const uint32_t*)&Wsm[n * WPITCH + cb];
                bb[1] = *(const uint32_t*)&Wsm[n * WPITCH + cb + 8];
                mma16816h(acc1[nj], a, bb);
            }
        }
    }

    // ---- kc = 2,3: acc1 += Agg @ W[:,128:256].T ; acc2 += Agg @ Wagg.T ----
#pragma unroll
    for (int kc = 0; kc < 2; kc++) {
#pragma unroll
        for (int s = 0; s < 4; s++) {
            uint32_t a[4];
            const __half* ab = g_agg + (m0 + mbase + gID) * (long long)FEATC
                             + kc * 64 + s * 16 + qid * 2;
#pragma unroll
            for (int rr = 0; rr < 2; rr++)
#pragma unroll
                for (int kk = 0; kk < 2; kk++)
                    a[rr + kk * 2] = *(const uint32_t*)(ab + rr * 8 * FEATC + kk * 8);
            int cb  = 128 + kc * 64 + s * 16 + qid * 2;
            int cb2 = kc * 64 + s * 16 + qid * 2;
#pragma unroll
            for (int nj = 0; nj < 8; nj++) {
                int n = nbase + nj * 8 + gID;
                uint32_t bb[2], cc[2];
                bb[0] = *(const uint32_t*)&Wsm[n * WPITCH + cb];
                bb[1] = *(const uint32_t*)&Wsm[n * WPITCH + cb + 8];
                cc[0] = *(const uint32_t*)&W2[n * W2PITCH + cb2];
                cc[1] = *(const uint32_t*)&W2[n * W2PITCH + cb2 + 8];
                mma16816h(acc1[nj], a, bb);
                mma16816h(acc2[nj], a, cc);
            }
        }
    }
    __syncthreads();   // sync 2: W2 region free for red/scales overlay

    // ---- epilogue ----
    float ss[2] = {0.f, 0.f};
#pragma unroll
    for (int rr = 0; rr < 2; rr++)
#pragma unroll
        for (int nj = 0; nj < 8; nj++) {
            int c = nbase + nj * 8 + qid * 2;
#pragma unroll
            for (int k = 0; k < 2; k++) {
                float t1 = acc1[nj][rr * 2 + k] + b[c + k];
                float t2 = acc2[nj][rr * 2 + k] + bagg[c + k];
                if (LAYER == 0) { t1 = leaky01(t1); t2 = leaky01(t2); }
                float v = t1 + t2;
                acc1[nj][rr * 2 + k] = v;
                if (LAYER == 0) ss[rr] = fmaf(v, v, ss[rr]);
            }
        }

    if (LAYER == 0) {
#pragma unroll
        for (int rr = 0; rr < 2; rr++) {
            float v = ss[rr];
            v += __shfl_xor_sync(0xFFFFFFFF, v, 1);
            v += __shfl_xor_sync(0xFFFFFFFF, v, 2);
            ss[rr] = v;
        }
        if (qid == 0) {
#pragma unroll
            for (int rr = 0; rr < 2; rr++) {
                int rl = mbase + rr * 8 + gID;
                red[rl * 2 + wn] = ss[rr];
            }
        }
        __syncthreads();
        if (tid < 64) {
            float s = red[tid * 2] + red[tid * 2 + 1];
            scales[tid] = 1.0f / fmaxf(sqrtf(s), 1e-6f);
        }
        __syncthreads();
#pragma unroll
        for (int rr = 0; rr < 2; rr++) {
            int rl = mbase + rr * 8 + gID;
            float sc = scales[rl];
            __half* orow = g_h1h + (m0 + rl) * (long long)FEATC;
#pragma unroll
            for (int nj = 0; nj < 8; nj++) {
                int c = nbase + nj * 8 + qid * 2;
                *(__half2*)(orow + c) = __floats2half2_rn(
                    acc1[nj][rr * 2 + 0] * sc, acc1[nj][rr * 2 + 1] * sc);
            }
        }
    } else {
#pragma unroll
        for (int rr = 0; rr < 2; rr++) {
            int rl = mbase + rr * 8 + gID;
            float* orow = dout + (m0 + rl) * (long long)FEATC;
#pragma unroll
            for (int nj = 0; nj < 8; nj++) {
                int c = nbase + nj * 8 + qid * 2;
                float2 o;
                o.x = acc1[nj][rr * 2 + 0];
                o.y = acc1[nj][rr * 2 + 1];
                *(float2*)(orow + c) = o;
            }
        }
    }
}

// ---------------------------------------------------------------------------
// kernel_launch
// ---------------------------------------------------------------------------
extern "C" void kernel_launch(void* const* d_in, const int* in_sizes, int n_in,
                              void* d_out, int out_size)
{
    const float* node_emb = (const float*)d_in[0];
    const float* content0 = (const float*)d_in[1];
    const float* Wp    = (const float*)d_in[2];
    const float* bp    = (const float*)d_in[3];
    const float* W0    = (const float*)d_in[4];
    const float* b0    = (const float*)d_in[5];
    const float* Wagg0 = (const float*)d_in[6];
    const float* bagg0 = (const float*)d_in[7];
    const float* W1    = (const float*)d_in[8];
    const float* b1    = (const float*)d_in[9];
    const float* Wagg1 = (const float*)d_in[10];
    const float* bagg1 = (const float*)d_in[11];
    const int* parent0 = (const int*)d_in[12];
    const int* src0    = (const int*)d_in[13];
    const int* src1    = (const int*)d_in[15];
    float* out = (float*)d_out;

    cudaFuncSetAttribute(k_h0_mma, cudaFuncAttributeMaxDynamicSharedMemorySize, H0_SMEM_BYTES);
    cudaFuncSetAttribute(k_conv_mma<0>, cudaFuncAttributeMaxDynamicSharedMemorySize, CONV_SMEM_BYTES);
    cudaFuncSetAttribute(k_conv_mma<1>, cudaFuncAttributeMaxDynamicSharedMemorySize, CONV_SMEM_BYTES);

    k_prep<<<(W_TOTAL + 255) / 256, 256>>>(Wp, W0, Wagg0, W1, Wagg1);
    k_h0_mma<<<S0C / 128, 256, H0_SMEM_BYTES>>>(content0, bp, node_emb, parent0);
    k_agg<0><<<S1C / 16, 256>>>(src0 + S1C);
    k_conv_mma<0><<<S1C / 64, 256, CONV_SMEM_BYTES>>>(b0, bagg0, nullptr);
    k_agg<1><<<S2C / 16, 256>>>(src1 + S2C);
    k_conv_mma<1><<<S2C / 64, 256, CONV_SMEM_BYTES>>>(b1, bagg1, out);
}

// round 13
// speedup vs baseline: 1.4916x; 1.4916x over previous
#include <cuda_runtime.h>
#include <cuda_fp16.h>
#include <cstdint>

// ---------------------------------------------------------------------------
// GraphSAGE with sampling, GB300 (compute_103 virtual arch -> no tcgen05).
// Round 13 = round 11 (best, 359us) + 32x32 conv warp tiles (B-fragment reuse
// x2 -> conv GEMM LDS traffic -40%). Round-12 split-gather reverted (it lost
// 186us: conv GEMM is LDS-bound, gather was fine fused).
// Env constraint: dynamic smem <= ~116 KB per CTA (conv uses 103,424 B).
// ---------------------------------------------------------------------------

#define FEATC 128
#define CONTC 256
#define S2C   8192
#define S1C   73728        /* S2*9 */
#define S0C   663552       /* S1*9 */

// weight pool offsets (elements)
#define OFF_WP    0
#define OFF_W0    32768
#define OFF_WAGG0 65536
#define OFF_W1    81920
#define OFF_WAGG1 114688
#define W_TOTAL   131072

__device__ __half g_h0h[(long long)S0C * FEATC];   // 169.9 MB scratch
__device__ __half g_h1h[(long long)S1C * FEATC];   // 18.9 MB scratch
__device__ __half g_w16[W_TOTAL];                  // fp16 weights (all 5)

static __device__ __forceinline__ float leaky01(float x) {
    return x < 0.0f ? 0.1f * x : x;
}
static __device__ __forceinline__ uint32_t h2u(__half2 h) {
    return *reinterpret_cast<uint32_t*>(&h);
}

// mma.sync m16n8k16 row.col f32.f16.f16.f32, accumulate in place
static __device__ __forceinline__ void mma16816h(
    float* c, const uint32_t* a, const uint32_t* b)
{
    asm volatile(
        "mma.sync.aligned.m16n8k16.row.col.f32.f16.f16.f32 "
        "{%0,%1,%2,%3}, {%4,%5,%6,%7}, {%8,%9}, {%0,%1,%2,%3};"
        : "+f"(c[0]), "+f"(c[1]), "+f"(c[2]), "+f"(c[3])
        : "r"(a[0]), "r"(a[1]), "r"(a[2]), "r"(a[3]),
          "r"(b[0]), "r"(b[1]));
}

// ---------------------------------------------------------------------------
// k_prep: fp16 conversion of all weight matrices.
// ---------------------------------------------------------------------------
__global__ void k_prep(const float* __restrict__ Wp, const float* __restrict__ W0,
                       const float* __restrict__ Wagg0, const float* __restrict__ W1,
                       const float* __restrict__ Wagg1)
{
    int i = blockIdx.x * blockDim.x + threadIdx.x;
    if (i >= W_TOTAL) return;
    float v;
    if      (i < OFF_W0)    v = Wp[i - OFF_WP];
    else if (i < OFF_WAGG0) v = W0[i - OFF_W0];
    else if (i < OFF_W1)    v = Wagg0[i - OFF_WAGG0];
    else if (i < OFF_WAGG1) v = W1[i - OFF_W1];
    else                    v = Wagg1[i - OFF_WAGG1];
    g_w16[i] = __float2half_rn(v);
}

// ---------------------------------------------------------------------------
// k_h0_mma: fp16 GEMM, CTA 128x128, whole Wp in smem, one sync. (unchanged)
// ---------------------------------------------------------------------------
#define WPITCH 264
#define H0_SMEM_BYTES (128 * WPITCH * 2)   /* 67,584 B */

__global__ __launch_bounds__(256, 2) void k_h0_mma(
    const float* __restrict__ content,   // [S0,256]
    const float* __restrict__ bp,        // [128]
    const float* __restrict__ node_emb,  // [N+1,128]
    const int*   __restrict__ parent)    // [S0]
{
    extern __shared__ __half Ws[];       // [128][WPITCH]

    const int tid  = threadIdx.x;
    const int lane = tid & 31;
    const int warp = tid >> 5;
    const int gID  = lane >> 2;
    const int qid  = lane & 3;
    const long long m0 = (long long)blockIdx.x * 128;
    const int mbase = warp * 16;

#pragma unroll
    for (int it = 0; it < 16; it++) {
        int g = tid + 256 * it;
        int n = g >> 5;
        int c = (g & 31) * 8;
        *(uint4*)&Ws[n * WPITCH + c] = *(const uint4*)(g_w16 + OFF_WP + n * CONTC + c);
    }

    float acc[16][4];
#pragma unroll
    for (int nj = 0; nj < 16; nj++)
#pragma unroll
        for (int t = 0; t < 4; t++) acc[nj][t] = 0.0f;

    __syncthreads();

#pragma unroll
    for (int kc = 0; kc < 4; kc++) {
#pragma unroll
        for (int s = 0; s < 4; s++) {
            uint32_t a[4];
            const float* abase = content + (m0 + mbase + gID) * (long long)CONTC
                               + kc * 64 + s * 16 + qid * 2;
#pragma unroll
            for (int rr = 0; rr < 2; rr++)
#pragma unroll
                for (int kk = 0; kk < 2; kk++) {
                    float2 v = *(const float2*)(abase + rr * 8 * CONTC + kk * 8);
                    a[rr + kk * 2] = h2u(__float22half2_rn(v));
                }
            int cb = kc * 64 + s * 16 + qid * 2;
#pragma unroll
            for (int nj = 0; nj < 16; nj++) {
                int n = nj * 8 + gID;
                uint32_t b[2];
                b[0] = *(const uint32_t*)&Ws[n * WPITCH + cb];
                b[1] = *(const uint32_t*)&Ws[n * WPITCH + cb + 8];
                mma16816h(acc[nj], a, b);
            }
        }
    }

#pragma unroll
    for (int rr = 0; rr < 2; rr++) {
        long long r = m0 + mbase + rr * 8 + gID;
        long long p = (long long)parent[r] + 1;
        const float* ne = node_emb + p * FEATC;
        __half* orow = g_h0h + r * FEATC;
#pragma unroll
        for (int nj = 0; nj < 16; nj++) {
            int c = nj * 8 + qid * 2;
            float2 bv = *(const float2*)(bp + c);
            float2 nv = *(const float2*)(ne + c);
            float ox = leaky01(acc[nj][rr * 2 + 0] + bv.x) + nv.x;
            float oy = leaky01(acc[nj][rr * 2 + 1] + bv.y) + nv.y;
            *(__half2*)(orow + c) = __floats2half2_rn(ox, oy);
        }
    }
}

// ---------------------------------------------------------------------------
// k_conv_mma<LAYER>: fused gather + GEMM, 64 dst rows per CTA.
// Warp tiles 32x32 (2 m-frags x 4 n-frags): each B fragment feeds 2 MMAs.
// W fully smem-resident; Wagg staged in 2 chunks. 4 syncs per CTA.
// Dynamic smem (bytes), total 103,424:
//   [0, 17408)          Sagg  half[64][136]
//   [17408, +67584)     Wsm   half[128][264]  (whole W, K=256)
//   [84992, +18432)     B2    half[128][72]   (Wagg chunk; red/scales overlay)
// ---------------------------------------------------------------------------
#define CPITCH 136
#define BPAD   72
#define CONV_SMEM_BYTES (17408 + 67584 + 18432)

template <int LAYER>
__global__ __launch_bounds__(256, 2) void k_conv_mma(
    const int*   __restrict__ nbr,   // random-edge srcs, nbr[8*dst + k]
    const float* __restrict__ b,     // [128]
    const float* __restrict__ bagg,  // [128]
    float*       __restrict__ dout)  // layer1 output
{
    extern __shared__ char smem[];
    __half* Sagg = (__half*)smem;                    // [64][CPITCH]
    __half* Wsm  = (__half*)(smem + 17408);          // [128][WPITCH]
    __half* B2   = (__half*)(smem + 84992);          // [128][BPAD]
    float* red    = (float*)(smem + 84992);          // [64][4], epilogue only
    float* scales = (float*)(smem + 84992 + 1024);   // [64]

    const int tid  = threadIdx.x;
    const int lane = tid & 31;
    const int warp = tid >> 5;
    const int wm   = warp & 1;           // 32-row m-block
    const int wn   = warp >> 1;          // 32-col n-block (0..3)
    const int gID  = lane >> 2;
    const int qid  = lane & 3;
    const long long m0 = (long long)blockIdx.x * 64;
    const int mbase = wm * 32;
    const int nbase = wn * 32;
    const int WOFF  = (LAYER == 0) ? OFF_W0 : OFF_W1;
    const int AOFF  = (LAYER == 0) ? OFF_WAGG0 : OFF_WAGG1;
    const __half* hsrc = (LAYER == 0) ? g_h0h : g_h1h;

    // ---- stage whole W [128x256] and Wagg chunk0 [128x64] ----
#pragma unroll
    for (int it = 0; it < 16; it++) {
        int g = tid + 256 * it;
        int n = g >> 5;
        int c = (g & 31) * 8;
        *(uint4*)&Wsm[n * WPITCH + c] = *(const uint4*)(g_w16 + WOFF + n * CONTC + c);
    }
#pragma unroll
    for (int it = 0; it < 4; it++) {
        int g = tid + 256 * it;
        int n = g >> 3;
        int c = (g & 7) * 8;
        *(uint4*)&B2[n * BPAD + c] = *(const uint4*)(g_w16 + AOFF + n * FEATC + c);
    }

    // ---- phase 1: gather-mean, 2 rows in flight per warp iteration ----
#pragma unroll
    for (int rp = 0; rp < 4; rp++) {
        int rr0 = warp + rp * 16;
        int rr1 = rr0 + 8;
        long long d0 = m0 + rr0, d1 = m0 + rr1;
        int4 ea0 = *(const int4*)(nbr + d0 * 8);
        int4 eb0 = *(const int4*)(nbr + d0 * 8 + 4);
        int4 ea1 = *(const int4*)(nbr + d1 * 8);
        int4 eb1 = *(const int4*)(nbr + d1 * 8 + 4);
        int idx0[8] = {ea0.x, ea0.y, ea0.z, ea0.w, eb0.x, eb0.y, eb0.z, eb0.w};
        int idx1[8] = {ea1.x, ea1.y, ea1.z, ea1.w, eb1.x, eb1.y, eb1.z, eb1.w};
        uint2 u0[8], u1[8];
#pragma unroll
        for (int k = 0; k < 8; k++)
            u0[k] = *(const uint2*)(hsrc + (long long)idx0[k] * FEATC + lane * 4);
#pragma unroll
        for (int k = 0; k < 8; k++)
            u1[k] = *(const uint2*)(hsrc + (long long)idx1[k] * FEATC + lane * 4);

        float4 s0 = make_float4(0.f, 0.f, 0.f, 0.f);
        float4 s1 = make_float4(0.f, 0.f, 0.f, 0.f);
#pragma unroll
        for (int k = 0; k < 8; k++) {
            float2 f0 = __half22float2(*(__half2*)&u0[k].x);
            float2 f1 = __half22float2(*(__half2*)&u0[k].y);
            s0.x += f0.x; s0.y += f0.y; s0.z += f1.x; s0.w += f1.y;
            float2 g0 = __half22float2(*(__half2*)&u1[k].x);
            float2 g1 = __half22float2(*(__half2*)&u1[k].y);
            s1.x += g0.x; s1.y += g0.y; s1.z += g1.x; s1.w += g1.y;
        }
        if (LAYER == 1) {
            uint2 a1 = *(const uint2*)(g_h1h + d0 * FEATC + lane * 4);
            uint2 c1 = *(const uint2*)(g_h0h + d0 * FEATC + lane * 4);
            uint2 a2 = *(const uint2*)(g_h1h + d1 * FEATC + lane * 4);
            uint2 c2 = *(const uint2*)(g_h0h + d1 * FEATC + lane * 4);
            float2 p0 = __half22float2(*(__half2*)&a1.x), p1 = __half22float2(*(__half2*)&a1.y);
            float2 q0 = __half22float2(*(__half2*)&c1.x), q1 = __half22float2(*(__half2*)&c1.y);
            s0.x += p0.x - q0.x; s0.y += p0.y - q0.y;
            s0.z += p1.x - q1.x; s0.w += p1.y - q1.y;
            float2 r0 = __half22float2(*(__half2*)&a2.x), r1 = __half22float2(*(__half2*)&a2.y);
            float2 t0 = __half22float2(*(__half2*)&c2.x), t1 = __half22float2(*(__half2*)&c2.y);
            s1.x += r0.x - t0.x; s1.y += r0.y - t0.y;
            s1.z += r1.x - t1.x; s1.w += r1.y - t1.y;
        }
        s0.x *= 0.125f; s0.y *= 0.125f; s0.z *= 0.125f; s0.w *= 0.125f;
        s1.x *= 0.125f; s1.y *= 0.125f; s1.z *= 0.125f; s1.w *= 0.125f;
        uint2 o0, o1;
        *(__half2*)&o0.x = __floats2half2_rn(s0.x, s0.y);
        *(__half2*)&o0.y = __floats2half2_rn(s0.z, s0.w);
        *(__half2*)&o1.x = __floats2half2_rn(s1.x, s1.y);
        *(__half2*)&o1.y = __floats2half2_rn(s1.z, s1.w);
        *(uint2*)&Sagg[rr0 * CPITCH + lane * 4] = o0;
        *(uint2*)&Sagg[rr1 * CPITCH + lane * 4] = o1;
    }

    float acc1[2][4][4], acc2[2][4][4];
#pragma unroll
    for (int mi = 0; mi < 2; mi++)
#pragma unroll
        for (int nj = 0; nj < 4; nj++)
#pragma unroll
            for (int t = 0; t < 4; t++) { acc1[mi][nj][t] = 0.f; acc2[mi][nj][t] = 0.f; }

    __syncthreads();   // sync 1: Sagg + Wsm + B2(chunk0) ready

    // ---- kc = 0,1: acc1 += X @ W[:,0:128].T ----
#pragma unroll
    for (int kc = 0; kc < 2; kc++) {
#pragma unroll
        for (int s = 0; s < 4; s++) {
            uint32_t a[2][4];
#pragma unroll
            for (int mi = 0; mi < 2; mi++) {
                const __half* ab = g_h0h + (m0 + mbase + mi * 16 + gID) * (long long)FEATC
                                 + kc * 64 + s * 16 + qid * 2;
#pragma unroll
                for (int rr = 0; rr < 2; rr++)
#pragma unroll
                    for (int kk = 0; kk < 2; kk++)
                        a[mi][rr + kk * 2] = *(const uint32_t*)(ab + rr * 8 * FEATC + kk * 8);
            }
            int cb = kc * 64 + s * 16 + qid * 2;
#pragma unroll
            for (int nj = 0; nj < 4; nj++) {
                int n = nbase + nj * 8 + gID;
                uint32_t bb[2];
                bb[0] = *(const uint32_t*)&Wsm[n * WPITCH + cb];
                bb[1] = *(const uint32_t*)&Wsm[n * WPITCH + cb + 8];
                mma16816h(acc1[0][nj], a[0], bb);
                mma16816h(acc1[1][nj], a[1], bb);
            }
        }
    }

    // ---- kc = 2: Agg @ (W[:,128:192] and Wagg[:,0:64]) ----
#pragma unroll
    for (int s = 0; s < 4; s++) {
        uint32_t a[2][4];
#pragma unroll
        for (int mi = 0; mi < 2; mi++) {
            const __half* ab = Sagg + (mbase + mi * 16 + gID) * CPITCH + s * 16 + qid * 2;
#pragma unroll
            for (int rr = 0; rr < 2; rr++)
#pragma unroll
                for (int kk = 0; kk < 2; kk++)
                    a[mi][rr + kk * 2] = *(const uint32_t*)(ab + rr * 8 * CPITCH + kk * 8);
        }
        int cb = 128 + s * 16 + qid * 2;
        int cb2 = s * 16 + qid * 2;
#pragma unroll
        for (int nj = 0; nj < 4; nj++) {
            int n = nbase + nj * 8 + gID;
            uint32_t bb[2], cc[2];
            bb[0] = *(const uint32_t*)&Wsm[n * WPITCH + cb];
            bb[1] = *(const uint32_t*)&Wsm[n * WPITCH + cb + 8];
            cc[0] = *(const uint32_t*)&B2[n * BPAD + cb2];
            cc[1] = *(const uint32_t*)&B2[n * BPAD + cb2 + 8];
            mma16816h(acc1[0][nj], a[0], bb);
            mma16816h(acc1[1][nj], a[1], bb);
            mma16816h(acc2[0][nj], a[0], cc);
            mma16816h(acc2[1][nj], a[1], cc);
        }
    }

    __syncthreads();   // sync 2: B2 chunk0 consumed
    // stage Wagg chunk1 [128 x 64] (cols 64..127)
#pragma unroll
    for (int it = 0; it < 4; it++) {
        int g = tid + 256 * it;
        int n = g >> 3;
        int c = (g & 7) * 8;
        *(uint4*)&B2[n * BPAD + c] = *(const uint4*)(g_w16 + AOFF + n * FEATC + 64 + c);
    }
    __syncthreads();   // sync 3: B2 chunk1 ready

    // ---- kc = 3: Agg @ (W[:,192:256] and Wagg[:,64:128]) ----
#pragma unroll
    for (int s = 0; s < 4; s++) {
        uint32_t a[2][4];
#pragma unroll
        for (int mi = 0; mi < 2; mi++) {
            const __half* ab = Sagg + (mbase + mi * 16 + gID) * CPITCH + 64 + s * 16 + qid * 2;
#pragma unroll
            for (int rr = 0; rr < 2; rr++)
#pragma unroll
                for (int kk = 0; kk < 2; kk++)
                    a[mi][rr + kk * 2] = *(const uint32_t*)(ab + rr * 8 * CPITCH + kk * 8);
        }
        int cb = 192 + s * 16 + qid * 2;
        int cb2 = s * 16 + qid * 2;
#pragma unroll
        for (int nj = 0; nj < 4; nj++) {
            int n = nbase + nj * 8 + gID;
            uint32_t bb[2], cc[2];
            bb[0] = *(const uint32_t*)&Wsm[n * WPITCH + cb];
            bb[1] = *(const uint32_t*)&Wsm[n * WPITCH + cb + 8];
            cc[0] = *(const uint32_t*)&B2[n * BPAD + cb2];
            cc[1] = *(const uint32_t*)&B2[n * BPAD + cb2 + 8];
            mma16816h(acc1[0][nj], a[0], bb);
            mma16816h(acc1[1][nj], a[1], bb);
            mma16816h(acc2[0][nj], a[0], cc);
            mma16816h(acc2[1][nj], a[1], cc);
        }
    }
    __syncthreads();   // sync 4: B2 region free for red/scales overlay

    // ---- epilogue ----
    float ss[2][2] = {{0.f, 0.f}, {0.f, 0.f}};
#pragma unroll
    for (int mi = 0; mi < 2; mi++)
#pragma unroll
        for (int rr = 0; rr < 2; rr++)
#pragma unroll
            for (int nj = 0; nj < 4; nj++) {
                int c = nbase + nj * 8 + qid * 2;
#pragma unroll
                for (int k = 0; k < 2; k++) {
                    float t1 = acc1[mi][nj][rr * 2 + k] + b[c + k];
                    float t2 = acc2[mi][nj][rr * 2 + k] + bagg[c + k];
                    if (LAYER == 0) { t1 = leaky01(t1); t2 = leaky01(t2); }
                    float v = t1 + t2;
                    acc1[mi][nj][rr * 2 + k] = v;
                    if (LAYER == 0) ss[mi][rr] = fmaf(v, v, ss[mi][rr]);
                }
            }

    if (LAYER == 0) {
        // reduce over the 4 qid lanes (same row), then across the 4 wn warps
#pragma unroll
        for (int mi = 0; mi < 2; mi++)
#pragma unroll
            for (int rr = 0; rr < 2; rr++) {
                float v = ss[mi][rr];
                v += __shfl_xor_sync(0xFFFFFFFF, v, 1);
                v += __shfl_xor_sync(0xFFFFFFFF, v, 2);
                ss[mi][rr] = v;
            }
        if (qid == 0) {
#pragma unroll
            for (int mi = 0; mi < 2; mi++)
#pragma unroll
                for (int rr = 0; rr < 2; rr++) {
                    int rl = mbase + mi * 16 + rr * 8 + gID;
                    red[rl * 4 + wn] = ss[mi][rr];
                }
        }
        __syncthreads();
        if (tid < 64) {
            float s = red[tid * 4] + red[tid * 4 + 1] + red[tid * 4 + 2] + red[tid * 4 + 3];
            scales[tid] = 1.0f / fmaxf(sqrtf(s), 1e-6f);
        }
        __syncthreads();
#pragma unroll
        for (int mi = 0; mi < 2; mi++)
#pragma unroll
            for (int rr = 0; rr < 2; rr++) {
                int rl = mbase + mi * 16 + rr * 8 + gID;
                float sc = scales[rl];
                __half* orow = g_h1h + (m0 + rl) * (long long)FEATC;
#pragma unroll
                for (int nj = 0; nj < 4; nj++) {
                    int c = nbase + nj * 8 + qid * 2;
                    *(__half2*)(orow + c) = __floats2half2_rn(
                        acc1[mi][nj][rr * 2 + 0] * sc, acc1[mi][nj][rr * 2 + 1] * sc);
                }
            }
    } else {
#pragma unroll
        for (int mi = 0; mi < 2; mi++)
#pragma unroll
            for (int rr = 0; rr < 2; rr++) {
                int rl = mbase + mi * 16 + rr * 8 + gID;
                float* orow = dout + (m0 + rl) * (long long)FEATC;
#pragma unroll
                for (int nj = 0; nj < 4; nj++) {
                    int c = nbase + nj * 8 + qid * 2;
                    float2 o;
                    o.x = acc1[mi][nj][rr * 2 + 0];
                    o.y = acc1[mi][nj][rr * 2 + 1];
                    *(float2*)(orow + c) = o;
                }
            }
    }
}

// ---------------------------------------------------------------------------
// kernel_launch
// ---------------------------------------------------------------------------
extern "C" void kernel_launch(void* const* d_in, const int* in_sizes, int n_in,
                              void* d_out, int out_size)
{
    const float* node_emb = (const float*)d_in[0];
    const float* content0 = (const float*)d_in[1];
    const float* Wp    = (const float*)d_in[2];
    const float* bp    = (const float*)d_in[3];
    const float* W0    = (const float*)d_in[4];
    const float* b0    = (const float*)d_in[5];
    const float* Wagg0 = (const float*)d_in[6];
    const float* bagg0 = (const float*)d_in[7];
    const float* W1    = (const float*)d_in[8];
    const float* b1    = (const float*)d_in[9];
    const float* Wagg1 = (const float*)d_in[10];
    const float* bagg1 = (const float*)d_in[11];
    const int* parent0 = (const int*)d_in[12];
    const int* src0    = (const int*)d_in[13];
    const int* src1    = (const int*)d_in[15];
    float* out = (float*)d_out;

    cudaFuncSetAttribute(k_h0_mma, cudaFuncAttributeMaxDynamicSharedMemorySize, H0_SMEM_BYTES);
    cudaFuncSetAttribute(k_conv_mma<0>, cudaFuncAttributeMaxDynamicSharedMemorySize, CONV_SMEM_BYTES);
    cudaFuncSetAttribute(k_conv_mma<1>, cudaFuncAttributeMaxDynamicSharedMemorySize, CONV_SMEM_BYTES);

    k_prep<<<(W_TOTAL + 255) / 256, 256>>>(Wp, W0, Wagg0, W1, Wagg1);
    k_h0_mma<<<S0C / 128, 256, H0_SMEM_BYTES>>>(content0, bp, node_emb, parent0);
    k_conv_mma<0><<<S1C / 64, 256, CONV_SMEM_BYTES>>>(src0 + S1C, b0, bagg0, nullptr);
    k_conv_mma<1><<<S2C / 64, 256, CONV_SMEM_BYTES>>>(src1 + S2C, b1, bagg1, out);
}

// round 14
// speedup vs baseline: 1.5162x; 1.0165x over previous
#include <cuda_runtime.h>
#include <cuda_fp16.h>
#include <cstdint>

// ---------------------------------------------------------------------------
// GraphSAGE with sampling, GB300 (compute_103 virtual arch -> no tcgen05).
// Round 14 = round 11 (best, 359us) + three latency fixes:
//  - h0: software-pipelined A loads (prefetch k-step s+1 before MMAs of s)
//  - h0: parent[] prefetched before mainloop (shortens epilogue tail)
//  - conv layer 1: 32-row CTAs -> grid 256 (all SMs busy; was 128 CTAs)
// Arithmetic identical to rounds 10-13 (rel_err 4.2e-4).
// Env constraint: dynamic smem <= ~116 KB per CTA (conv uses 103,424 B).
// ---------------------------------------------------------------------------

#define FEATC 128
#define CONTC 256
#define S2C   8192
#define S1C   73728        /* S2*9 */
#define S0C   663552       /* S1*9 */

// weight pool offsets (elements)
#define OFF_WP    0
#define OFF_W0    32768
#define OFF_WAGG0 65536
#define OFF_W1    81920
#define OFF_WAGG1 114688
#define W_TOTAL   131072

__device__ __half g_h0h[(long long)S0C * FEATC];   // 169.9 MB scratch
__device__ __half g_h1h[(long long)S1C * FEATC];   // 18.9 MB scratch
__device__ __half g_w16[W_TOTAL];                  // fp16 weights (all 5)

static __device__ __forceinline__ float leaky01(float x) {
    return x < 0.0f ? 0.1f * x : x;
}
static __device__ __forceinline__ uint32_t h2u(__half2 h) {
    return *reinterpret_cast<uint32_t*>(&h);
}

// mma.sync m16n8k16 row.col f32.f16.f16.f32, accumulate in place
static __device__ __forceinline__ void mma16816h(
    float* c, const uint32_t* a, const uint32_t* b)
{
    asm volatile(
        "mma.sync.aligned.m16n8k16.row.col.f32.f16.f16.f32 "
        "{%0,%1,%2,%3}, {%4,%5,%6,%7}, {%8,%9}, {%0,%1,%2,%3};"
        : "+f"(c[0]), "+f"(c[1]), "+f"(c[2]), "+f"(c[3])
        : "r"(a[0]), "r"(a[1]), "r"(a[2]), "r"(a[3]),
          "r"(b[0]), "r"(b[1]));
}

// ---------------------------------------------------------------------------
// k_prep: fp16 conversion of all weight matrices.
// ---------------------------------------------------------------------------
__global__ void k_prep(const float* __restrict__ Wp, const float* __restrict__ W0,
                       const float* __restrict__ Wagg0, const float* __restrict__ W1,
                       const float* __restrict__ Wagg1)
{
    int i = blockIdx.x * blockDim.x + threadIdx.x;
    if (i >= W_TOTAL) return;
    float v;
    if      (i < OFF_W0)    v = Wp[i - OFF_WP];
    else if (i < OFF_WAGG0) v = W0[i - OFF_W0];
    else if (i < OFF_W1)    v = Wagg0[i - OFF_WAGG0];
    else if (i < OFF_WAGG1) v = W1[i - OFF_W1];
    else                    v = Wagg1[i - OFF_WAGG1];
    g_w16[i] = __float2half_rn(v);
}

// ---------------------------------------------------------------------------
// k_h0_mma: fp16 GEMM, CTA 128x128, whole Wp in smem, one sync.
// Software-pipelined A loads; parent prefetched before mainloop.
// ---------------------------------------------------------------------------
#define WPITCH 264
#define H0_SMEM_BYTES (128 * WPITCH * 2)   /* 67,584 B */

__global__ __launch_bounds__(256, 2) void k_h0_mma(
    const float* __restrict__ content,   // [S0,256]
    const float* __restrict__ bp,        // [128]
    const float* __restrict__ node_emb,  // [N+1,128]
    const int*   __restrict__ parent)    // [S0]
{
    extern __shared__ __half Ws[];       // [128][WPITCH]

    const int tid  = threadIdx.x;
    const int lane = tid & 31;
    const int warp = tid >> 5;
    const int gID  = lane >> 2;
    const int qid  = lane & 3;
    const long long m0 = (long long)blockIdx.x * 128;
    const int mbase = warp * 16;

#pragma unroll
    for (int it = 0; it < 16; it++) {
        int g = tid + 256 * it;
        int n = g >> 5;
        int c = (g & 31) * 8;
        *(uint4*)&Ws[n * WPITCH + c] = *(const uint4*)(g_w16 + OFF_WP + n * CONTC + c);
    }

    // early loads: parent indices for this thread's two output rows
    const long long r0e = m0 + mbase + gID;
    const long long r1e = r0e + 8;
    const long long p0 = (long long)parent[r0e] + 1;
    const long long p1 = (long long)parent[r1e] + 1;

    float acc[16][4];
#pragma unroll
    for (int nj = 0; nj < 16; nj++)
#pragma unroll
        for (int t = 0; t < 4; t++) acc[nj][t] = 0.0f;

    // prefetch A for k-step 0 (global loads, independent of Ws)
    const float* abase = content + (m0 + mbase + gID) * (long long)CONTC + qid * 2;
    float2 f_cur[4], f_nxt[4];
#pragma unroll
    for (int rr = 0; rr < 2; rr++)
#pragma unroll
        for (int kk = 0; kk < 2; kk++)
            f_cur[rr + kk * 2] = *(const float2*)(abase + rr * 8 * CONTC + kk * 8);

    __syncthreads();

#pragma unroll
    for (int st = 0; st < 16; st++) {
        if (st < 15) {
#pragma unroll
            for (int rr = 0; rr < 2; rr++)
#pragma unroll
                for (int kk = 0; kk < 2; kk++)
                    f_nxt[rr + kk * 2] =
                        *(const float2*)(abase + (st + 1) * 16 + rr * 8 * CONTC + kk * 8);
        }
        uint32_t a[4];
#pragma unroll
        for (int t = 0; t < 4; t++) a[t] = h2u(__float22half2_rn(f_cur[t]));
        int cb = st * 16 + qid * 2;
#pragma unroll
        for (int nj = 0; nj < 16; nj++) {
            int n = nj * 8 + gID;
            uint32_t b[2];
            b[0] = *(const uint32_t*)&Ws[n * WPITCH + cb];
            b[1] = *(const uint32_t*)&Ws[n * WPITCH + cb + 8];
            mma16816h(acc[nj], a, b);
        }
        if (st < 15) {
#pragma unroll
            for (int t = 0; t < 4; t++) f_cur[t] = f_nxt[t];
        }
    }

    // epilogue: bias + leaky + node_emb gather -> g_h0h (fp16)
#pragma unroll
    for (int rr = 0; rr < 2; rr++) {
        long long r = (rr == 0) ? r0e : r1e;
        long long p = (rr == 0) ? p0 : p1;
        const float* ne = node_emb + p * FEATC;
        __half* orow = g_h0h + r * FEATC;
#pragma unroll
        for (int nj = 0; nj < 16; nj++) {
            int c = nj * 8 + qid * 2;
            float2 bv = *(const float2*)(bp + c);
            float2 nv = *(const float2*)(ne + c);
            float ox = leaky01(acc[nj][rr * 2 + 0] + bv.x) + nv.x;
            float oy = leaky01(acc[nj][rr * 2 + 1] + bv.y) + nv.y;
            *(__half2*)(orow + c) = __floats2half2_rn(ox, oy);
        }
    }
}

// ---------------------------------------------------------------------------
// k_conv_mma<LAYER>: fused gather + GEMM.
//  LAYER 0: ROWS=64 per CTA (exact round-11 shape: 4m x 2n warps, 16x64 tiles)
//  LAYER 1: ROWS=32 per CTA (2m x 4n warps, 16x32 tiles) -> grid 256
// W fully smem-resident; Wagg staged in 2 chunks. 4 syncs per CTA.
// Dynamic smem (bytes), total 103,424:
//   [0, 17408)          Sagg  half[64][136]
//   [17408, +67584)     Wsm   half[128][264]
//   [84992, +18432)     B2    half[128][72]   (red/scales overlay in epilogue)
// ---------------------------------------------------------------------------
#define CPITCH 136
#define BPAD   72
#define CONV_SMEM_BYTES (17408 + 67584 + 18432)

template <int LAYER>
__global__ __launch_bounds__(256, 2) void k_conv_mma(
    const int*   __restrict__ nbr,   // random-edge srcs, nbr[8*dst + k]
    const float* __restrict__ b,     // [128]
    const float* __restrict__ bagg,  // [128]
    float*       __restrict__ dout)  // layer1 output
{
    constexpr int ROWS = (LAYER == 0) ? 64 : 32;
    constexpr int NWN  = (LAYER == 0) ? 2 : 4;    // n-block warps
    constexpr int NWM  = 8 / NWN;                 // m-block warps
    constexpr int NJ   = 128 / (NWN * 8);         // n-frags per warp (8 or 4)

    extern __shared__ char smem[];
    __half* Sagg = (__half*)smem;                    // [<=64][CPITCH]
    __half* Wsm  = (__half*)(smem + 17408);          // [128][WPITCH]
    __half* B2   = (__half*)(smem + 84992);          // [128][BPAD]
    float* red    = (float*)(smem + 84992);          // epilogue only (L0)
    float* scales = (float*)(smem + 84992 + 512);    // (L0)

    const int tid  = threadIdx.x;
    const int lane = tid & 31;
    const int warp = tid >> 5;
    const int wm   = warp % NWM;
    const int wn   = warp / NWM;
    const int gID  = lane >> 2;
    const int qid  = lane & 3;
    const long long m0 = (long long)blockIdx.x * ROWS;
    const int mbase = wm * 16;
    const int nbase = wn * (NJ * 8);
    const int WOFF  = (LAYER == 0) ? OFF_W0 : OFF_W1;
    const int AOFF  = (LAYER == 0) ? OFF_WAGG0 : OFF_WAGG1;
    const __half* hsrc = (LAYER == 0) ? g_h0h : g_h1h;

    // ---- stage whole W [128x256] and Wagg chunk0 [128x64] ----
#pragma unroll
    for (int it = 0; it < 16; it++) {
        int g = tid + 256 * it;
        int n = g >> 5;
        int c = (g & 31) * 8;
        *(uint4*)&Wsm[n * WPITCH + c] = *(const uint4*)(g_w16 + WOFF + n * CONTC + c);
    }
#pragma unroll
    for (int it = 0; it < 4; it++) {
        int g = tid + 256 * it;
        int n = g >> 3;
        int c = (g & 7) * 8;
        *(uint4*)&B2[n * BPAD + c] = *(const uint4*)(g_w16 + AOFF + n * FEATC + c);
    }

    // ---- phase 1: gather-mean, 2 rows in flight per warp iteration ----
#pragma unroll
    for (int rp = 0; rp < ROWS / 16; rp++) {
        int rr0 = warp + rp * 16;
        int rr1 = rr0 + 8;
        long long d0 = m0 + rr0, d1 = m0 + rr1;
        int4 ea0 = *(const int4*)(nbr + d0 * 8);
        int4 eb0 = *(const int4*)(nbr + d0 * 8 + 4);
        int4 ea1 = *(const int4*)(nbr + d1 * 8);
        int4 eb1 = *(const int4*)(nbr + d1 * 8 + 4);
        int idx0[8] = {ea0.x, ea0.y, ea0.z, ea0.w, eb0.x, eb0.y, eb0.z, eb0.w};
        int idx1[8] = {ea1.x, ea1.y, ea1.z, ea1.w, eb1.x, eb1.y, eb1.z, eb1.w};
        uint2 u0[8], u1[8];
#pragma unroll
        for (int k = 0; k < 8; k++)
            u0[k] = *(const uint2*)(hsrc + (long long)idx0[k] * FEATC + lane * 4);
#pragma unroll
        for (int k = 0; k < 8; k++)
            u1[k] = *(const uint2*)(hsrc + (long long)idx1[k] * FEATC + lane * 4);

        float4 s0 = make_float4(0.f, 0.f, 0.f, 0.f);
        float4 s1 = make_float4(0.f, 0.f, 0.f, 0.f);
#pragma unroll
        for (int k = 0; k < 8; k++) {
            float2 f0 = __half22float2(*(__half2*)&u0[k].x);
            float2 f1 = __half22float2(*(__half2*)&u0[k].y);
            s0.x += f0.x; s0.y += f0.y; s0.z += f1.x; s0.w += f1.y;
            float2 g0 = __half22float2(*(__half2*)&u1[k].x);
            float2 g1 = __half22float2(*(__half2*)&u1[k].y);
            s1.x += g0.x; s1.y += g0.y; s1.z += g1.x; s1.w += g1.y;
        }
        if (LAYER == 1) {
            uint2 a1 = *(const uint2*)(g_h1h + d0 * FEATC + lane * 4);
            uint2 c1 = *(const uint2*)(g_h0h + d0 * FEATC + lane * 4);
            uint2 a2 = *(const uint2*)(g_h1h + d1 * FEATC + lane * 4);
            uint2 c2 = *(const uint2*)(g_h0h + d1 * FEATC + lane * 4);
            float2 p0 = __half22float2(*(__half2*)&a1.x), p1 = __half22float2(*(__half2*)&a1.y);
            float2 q0 = __half22float2(*(__half2*)&c1.x), q1 = __half22float2(*(__half2*)&c1.y);
            s0.x += p0.x - q0.x; s0.y += p0.y - q0.y;
            s0.z += p1.x - q1.x; s0.w += p1.y - q1.y;
            float2 r0 = __half22float2(*(__half2*)&a2.x), r1 = __half22float2(*(__half2*)&a2.y);
            float2 t0 = __half22float2(*(__half2*)&c2.x), t1 = __half22float2(*(__half2*)&c2.y);
            s1.x += r0.x - t0.x; s1.y += r0.y - t0.y;
            s1.z += r1.x - t1.x; s1.w += r1.y - t1.y;
        }
        s0.x *= 0.125f; s0.y *= 0.125f; s0.z *= 0.125f; s0.w *= 0.125f;
        s1.x *= 0.125f; s1.y *= 0.125f; s1.z *= 0.125f; s1.w *= 0.125f;
        uint2 o0, o1;
        *(__half2*)&o0.x = __floats2half2_rn(s0.x, s0.y);
        *(__half2*)&o0.y = __floats2half2_rn(s0.z, s0.w);
        *(__half2*)&o1.x = __floats2half2_rn(s1.x, s1.y);
        *(__half2*)&o1.y = __floats2half2_rn(s1.z, s1.w);
        *(uint2*)&Sagg[rr0 * CPITCH + lane * 4] = o0;
        *(uint2*)&Sagg[rr1 * CPITCH + lane * 4] = o1;
    }

    float acc1[NJ][4], acc2[NJ][4];
#pragma unroll
    for (int nj = 0; nj < NJ; nj++)
#pragma unroll
        for (int t = 0; t < 4; t++) { acc1[nj][t] = 0.f; acc2[nj][t] = 0.f; }

    __syncthreads();   // sync 1: Sagg + Wsm + B2(chunk0) ready

    // ---- kc = 0,1: acc1 += X @ W[:,0:128].T ----
#pragma unroll
    for (int kc = 0; kc < 2; kc++) {
#pragma unroll
        for (int s = 0; s < 4; s++) {
            uint32_t a[4];
            const __half* ab = g_h0h + (m0 + mbase + gID) * (long long)FEATC
                             + kc * 64 + s * 16 + qid * 2;
#pragma unroll
            for (int rr = 0; rr < 2; rr++)
#pragma unroll
                for (int kk = 0; kk < 2; kk++)
                    a[rr + kk * 2] = *(const uint32_t*)(ab + rr * 8 * FEATC + kk * 8);
            int cb = kc * 64 + s * 16 + qid * 2;
#pragma unroll
            for (int nj = 0; nj < NJ; nj++) {
                int n = nbase + nj * 8 + gID;
                uint32_t bb[2];
                bb[0] = *(const uint32_t*)&Wsm[n * WPITCH + cb];
                bb[1] = *(const uint32_t*)&Wsm[n * WPITCH + cb + 8];
                mma16816h(acc1[nj], a, bb);
            }
        }
    }

    // ---- kc = 2: Agg @ (W[:,128:192] and Wagg[:,0:64]) ----
#pragma unroll
    for (int s = 0; s < 4; s++) {
        uint32_t a[4];
        const __half* ab = Sagg + (mbase + gID) * CPITCH + s * 16 + qid * 2;
#pragma unroll
        for (int rr = 0; rr < 2; rr++)
#pragma unroll
            for (int kk = 0; kk < 2; kk++)
                a[rr + kk * 2] = *(const uint32_t*)(ab + rr * 8 * CPITCH + kk * 8);
        int cb = 128 + s * 16 + qid * 2;
        int cb2 = s * 16 + qid * 2;
#pragma unroll
        for (int nj = 0; nj < NJ; nj++) {
            int n = nbase + nj * 8 + gID;
            uint32_t bb[2], cc[2];
            bb[0] = *(const uint32_t*)&Wsm[n * WPITCH + cb];
            bb[1] = *(const uint32_t*)&Wsm[n * WPITCH + cb + 8];
            cc[0] = *(const uint32_t*)&B2[n * BPAD + cb2];
            cc[1] = *(const uint32_t*)&B2[n * BPAD + cb2 + 8];
            mma16816h(acc1[nj], a, bb);
            mma16816h(acc2[nj], a, cc);
        }
    }

    __syncthreads();   // sync 2: B2 chunk0 consumed
    // stage Wagg chunk1 [128 x 64] (cols 64..127)
#pragma unroll
    for (int it = 0; it < 4; it++) {
        int g = tid + 256 * it;
        int n = g >> 3;
        int c = (g & 7) * 8;
        *(uint4*)&B2[n * BPAD + c] = *(const uint4*)(g_w16 + AOFF + n * FEATC + 64 + c);
    }
    __syncthreads();   // sync 3: B2 chunk1 ready

    // ---- kc = 3: Agg @ (W[:,192:256] and Wagg[:,64:128]) ----
#pragma unroll
    for (int s = 0; s < 4; s++) {
        uint32_t a[4];
        const __half* ab = Sagg + (mbase + gID) * CPITCH + 64 + s * 16 + qid * 2;
#pragma unroll
        for (int rr = 0; rr < 2; rr++)
#pragma unroll
            for (int kk = 0; kk < 2; kk++)
                a[rr + kk * 2] = *(const uint32_t*)(ab + rr * 8 * CPITCH + kk * 8);
        int cb = 192 + s * 16 + qid * 2;
        int cb2 = s * 16 + qid * 2;
#pragma unroll
        for (int nj = 0; nj < NJ; nj++) {
            int n = nbase + nj * 8 + gID;
            uint32_t bb[2], cc[2];
            bb[0] = *(const uint32_t*)&Wsm[n * WPITCH + cb];
            bb[1] = *(const uint32_t*)&Wsm[n * WPITCH + cb + 8];
            cc[0] = *(const uint32_t*)&B2[n * BPAD + cb2];
            cc[1] = *(const uint32_t*)&B2[n * BPAD + cb2 + 8];
            mma16816h(acc1[nj], a, bb);
            mma16816h(acc2[nj], a, cc);
        }
    }
    __syncthreads();   // sync 4: B2 region free for red/scales overlay

    // ---- epilogue ----
    float ss[2] = {0.f, 0.f};
#pragma unroll
    for (int rr = 0; rr < 2; rr++)
#pragma unroll
        for (int nj = 0; nj < NJ; nj++) {
            int c = nbase + nj * 8 + qid * 2;
#pragma unroll
            for (int k = 0; k < 2; k++) {
                float t1 = acc1[nj][rr * 2 + k] + b[c + k];
                float t2 = acc2[nj][rr * 2 + k] + bagg[c + k];
                if (LAYER == 0) { t1 = leaky01(t1); t2 = leaky01(t2); }
                float v = t1 + t2;
                acc1[nj][rr * 2 + k] = v;
                if (LAYER == 0) ss[rr] = fmaf(v, v, ss[rr]);
            }
        }

    if (LAYER == 0) {
        // reduce over qid lanes, then across the 2 n-block warps via smem
#pragma unroll
        for (int rr = 0; rr < 2; rr++) {
            float v = ss[rr];
            v += __shfl_xor_sync(0xFFFFFFFF, v, 1);
            v += __shfl_xor_sync(0xFFFFFFFF, v, 2);
            ss[rr] = v;
        }
        if (qid == 0) {
#pragma unroll
            for (int rr = 0; rr < 2; rr++) {
                int rl = mbase + rr * 8 + gID;
                red[rl * 2 + wn] = ss[rr];
            }
        }
        __syncthreads();
        if (tid < 64) {
            float s = red[tid * 2] + red[tid * 2 + 1];
            scales[tid] = 1.0f / fmaxf(sqrtf(s), 1e-6f);
        }
        __syncthreads();
#pragma unroll
        for (int rr = 0; rr < 2; rr++) {
            int rl = mbase + rr * 8 + gID;
            float sc = scales[rl];
            __half* orow = g_h1h + (m0 + rl) * (long long)FEATC;
#pragma unroll
            for (int nj = 0; nj < NJ; nj++) {
                int c = nbase + nj * 8 + qid * 2;
                *(__half2*)(orow + c) = __floats2half2_rn(
                    acc1[nj][rr * 2 + 0] * sc, acc1[nj][rr * 2 + 1] * sc);
            }
        }
    } else {
#pragma unroll
        for (int rr = 0; rr < 2; rr++) {
            int rl = mbase + rr * 8 + gID;
            float* orow = dout + (m0 + rl) * (long long)FEATC;
#pragma unroll
            for (int nj = 0; nj < NJ; nj++) {
                int c = nbase + nj * 8 + qid * 2;
                float2 o;
                o.x = acc1[nj][rr * 2 + 0];
                o.y = acc1[nj][rr * 2 + 1];
                *(float2*)(orow + c) = o;
            }
        }
    }
}

// ---------------------------------------------------------------------------
// kernel_launch
// ---------------------------------------------------------------------------
extern "C" void kernel_launch(void* const* d_in, const int* in_sizes, int n_in,
                              void* d_out, int out_size)
{
    const float* node_emb = (const float*)d_in[0];
    const float* content0 = (const float*)d_in[1];
    const float* Wp    = (const float*)d_in[2];
    const float* bp    = (const float*)d_in[3];
    const float* W0    = (const float*)d_in[4];
    const float* b0    = (const float*)d_in[5];
    const float* Wagg0 = (const float*)d_in[6];
    const float* bagg0 = (const float*)d_in[7];
    const float* W1    = (const float*)d_in[8];
    const float* b1    = (const float*)d_in[9];
    const float* Wagg1 = (const float*)d_in[10];
    const float* bagg1 = (const float*)d_in[11];
    const int* parent0 = (const int*)d_in[12];
    const int* src0    = (const int*)d_in[13];
    const int* src1    = (const int*)d_in[15];
    float* out = (float*)d_out;

    cudaFuncSetAttribute(k_h0_mma, cudaFuncAttributeMaxDynamicSharedMemorySize, H0_SMEM_BYTES);
    cudaFuncSetAttribute(k_conv_mma<0>, cudaFuncAttributeMaxDynamicSharedMemorySize, CONV_SMEM_BYTES);
    cudaFuncSetAttribute(k_conv_mma<1>, cudaFuncAttributeMaxDynamicSharedMemorySize, CONV_SMEM_BYTES);

    k_prep<<<(W_TOTAL + 255) / 256, 256>>>(Wp, W0, Wagg0, W1, Wagg1);
    k_h0_mma<<<S0C / 128, 256, H0_SMEM_BYTES>>>(content0, bp, node_emb, parent0);
    k_conv_mma<0><<<S1C / 64, 256, CONV_SMEM_BYTES>>>(src0 + S1C, b0, bagg0, nullptr);
    k_conv_mma<1><<<S2C / 32, 256, CONV_SMEM_BYTES>>>(src1 + S2C, b1, bagg1, out);
}

// round 15
// speedup vs baseline: 1.6823x; 1.1096x over previous
#include <cuda_runtime.h>
#include <cuda_fp16.h>
#include <cstdint>

// ---------------------------------------------------------------------------
// GraphSAGE with sampling, GB300 (compute_103 virtual arch -> no tcgen05).
// Round 15 = round 14 + dead-row elimination in h0:
//  rows >= S1 of h0 are only consumed if hit by a random src0 edge
//  (coverage 1-e^{-8/9} ~ 58.9%). A scatter-built mask lets h0 skip the
//  content read / node_emb gather / store for ~242k dead rows (-36% traffic).
// Arithmetic for live rows identical to rounds 10-14 (rel_err 4.2e-4).
// Env constraint: dynamic smem <= ~116 KB per CTA.
// ---------------------------------------------------------------------------

#define FEATC 128
#define CONTC 256
#define S2C   8192
#define S1C   73728        /* S2*9 */
#define S0C   663552       /* S1*9 */

// weight pool offsets (elements)
#define OFF_WP    0
#define OFF_W0    32768
#define OFF_WAGG0 65536
#define OFF_W1    81920
#define OFF_WAGG1 114688
#define W_TOTAL   131072

__device__ __half g_h0h[(long long)S0C * FEATC];   // 169.9 MB scratch
__device__ __half g_h1h[(long long)S1C * FEATC];   // 18.9 MB scratch
__device__ __half g_w16[W_TOTAL];                  // fp16 weights (all 5)
__device__ unsigned char g_mask[S0C];              // h0-row liveness

static __device__ __forceinline__ float leaky01(float x) {
    return x < 0.0f ? 0.1f * x : x;
}
static __device__ __forceinline__ uint32_t h2u(__half2 h) {
    return *reinterpret_cast<uint32_t*>(&h);
}

// mma.sync m16n8k16 row.col f32.f16.f16.f32, accumulate in place
static __device__ __forceinline__ void mma16816h(
    float* c, const uint32_t* a, const uint32_t* b)
{
    asm volatile(
        "mma.sync.aligned.m16n8k16.row.col.f32.f16.f16.f32 "
        "{%0,%1,%2,%3}, {%4,%5,%6,%7}, {%8,%9}, {%0,%1,%2,%3};"
        : "+f"(c[0]), "+f"(c[1]), "+f"(c[2]), "+f"(c[3])
        : "r"(a[0]), "r"(a[1]), "r"(a[2]), "r"(a[3]),
          "r"(b[0]), "r"(b[1]));
}

// ---------------------------------------------------------------------------
// mask kernels: zero, then scatter 1s at random-edge targets of src0.
// Deterministic (all writers store 1); rebuilt every launch.
// ---------------------------------------------------------------------------
__global__ void k_mask_zero()
{
    int i = blockIdx.x * blockDim.x + threadIdx.x;
    if (i < S0C / 4) ((uint32_t*)g_mask)[i] = 0u;
}
__global__ void k_mask_set(const int* __restrict__ rand_src)   // 8*S1C entries
{
    int i = blockIdx.x * blockDim.x + threadIdx.x;
    if (i < 8 * S1C) g_mask[rand_src[i]] = 1;
}

// ---------------------------------------------------------------------------
// k_prep: fp16 conversion of all weight matrices.
// ---------------------------------------------------------------------------
__global__ void k_prep(const float* __restrict__ Wp, const float* __restrict__ W0,
                       const float* __restrict__ Wagg0, const float* __restrict__ W1,
                       const float* __restrict__ Wagg1)
{
    int i = blockIdx.x * blockDim.x + threadIdx.x;
    if (i >= W_TOTAL) return;
    float v;
    if      (i < OFF_W0)    v = Wp[i - OFF_WP];
    else if (i < OFF_WAGG0) v = W0[i - OFF_W0];
    else if (i < OFF_W1)    v = Wagg0[i - OFF_WAGG0];
    else if (i < OFF_WAGG1) v = W1[i - OFF_W1];
    else                    v = Wagg1[i - OFF_WAGG1];
    g_w16[i] = __float2half_rn(v);
}

// ---------------------------------------------------------------------------
// k_h0_mma: fp16 GEMM, CTA 128x128, whole Wp in smem, one sync.
// Dead rows (mask==0, row>=S1) skip content loads, node_emb gather, store.
// ---------------------------------------------------------------------------
#define WPITCH 264
#define H0_SMEM_BYTES (128 * WPITCH * 2)   /* 67,584 B */

__global__ __launch_bounds__(256, 2) void k_h0_mma(
    const float* __restrict__ content,   // [S0,256]
    const float* __restrict__ bp,        // [128]
    const float* __restrict__ node_emb,  // [N+1,128]
    const int*   __restrict__ parent)    // [S0]
{
    extern __shared__ __half Ws[];       // [128][WPITCH]

    const int tid  = threadIdx.x;
    const int lane = tid & 31;
    const int warp = tid >> 5;
    const int gID  = lane >> 2;
    const int qid  = lane & 3;
    const long long m0 = (long long)blockIdx.x * 128;
    const int mbase = warp * 16;

#pragma unroll
    for (int it = 0; it < 16; it++) {
        int g = tid + 256 * it;
        int n = g >> 5;
        int c = (g & 31) * 8;
        *(uint4*)&Ws[n * WPITCH + c] = *(const uint4*)(g_w16 + OFF_WP + n * CONTC + c);
    }

    // liveness + parent for this thread's two output rows
    const long long r0e = m0 + mbase + gID;
    const long long r1e = r0e + 8;
    const bool use0 = (r0e < S1C) || (g_mask[r0e] != 0);
    const bool use1 = (r1e < S1C) || (g_mask[r1e] != 0);
    const long long p0 = use0 ? (long long)parent[r0e] + 1 : 0;
    const long long p1 = use1 ? (long long)parent[r1e] + 1 : 0;

    float acc[16][4];
#pragma unroll
    for (int nj = 0; nj < 16; nj++)
#pragma unroll
        for (int t = 0; t < 4; t++) acc[nj][t] = 0.0f;

    // prefetch A for k-step 0 (predicated on row liveness)
    const float* abase = content + (m0 + mbase + gID) * (long long)CONTC + qid * 2;
    const float2 zz = make_float2(0.f, 0.f);
    float2 f_cur[4], f_nxt[4];
#pragma unroll
    for (int kk = 0; kk < 2; kk++) {
        f_cur[0 + kk * 2] = use0 ? *(const float2*)(abase + kk * 8) : zz;
        f_cur[1 + kk * 2] = use1 ? *(const float2*)(abase + 8 * CONTC + kk * 8) : zz;
    }

    __syncthreads();

#pragma unroll
    for (int st = 0; st < 16; st++) {
        if (st < 15) {
#pragma unroll
            for (int kk = 0; kk < 2; kk++) {
                f_nxt[0 + kk * 2] = use0 ?
                    *(const float2*)(abase + (st + 1) * 16 + kk * 8) : zz;
                f_nxt[1 + kk * 2] = use1 ?
                    *(const float2*)(abase + (st + 1) * 16 + 8 * CONTC + kk * 8) : zz;
            }
        }
        uint32_t a[4];
#pragma unroll
        for (int t = 0; t < 4; t++) a[t] = h2u(__float22half2_rn(f_cur[t]));
        int cb = st * 16 + qid * 2;
#pragma unroll
        for (int nj = 0; nj < 16; nj++) {
            int n = nj * 8 + gID;
            uint32_t b[2];
            b[0] = *(const uint32_t*)&Ws[n * WPITCH + cb];
            b[1] = *(const uint32_t*)&Ws[n * WPITCH + cb + 8];
            mma16816h(acc[nj], a, b);
        }
        if (st < 15) {
#pragma unroll
            for (int t = 0; t < 4; t++) f_cur[t] = f_nxt[t];
        }
    }

    // epilogue: bias + leaky + node_emb gather -> g_h0h (live rows only)
#pragma unroll
    for (int rr = 0; rr < 2; rr++) {
        const bool u = (rr == 0) ? use0 : use1;
        if (!u) continue;
        long long r = (rr == 0) ? r0e : r1e;
        long long p = (rr == 0) ? p0 : p1;
        const float* ne = node_emb + p * FEATC;
        __half* orow = g_h0h + r * FEATC;
#pragma unroll
        for (int nj = 0; nj < 16; nj++) {
            int c = nj * 8 + qid * 2;
            float2 bv = *(const float2*)(bp + c);
            float2 nv = *(const float2*)(ne + c);
            float ox = leaky01(acc[nj][rr * 2 + 0] + bv.x) + nv.x;
            float oy = leaky01(acc[nj][rr * 2 + 1] + bv.y) + nv.y;
            *(__half2*)(orow + c) = __floats2half2_rn(ox, oy);
        }
    }
}

// ---------------------------------------------------------------------------
// k_conv_mma<LAYER>: fused gather + GEMM (unchanged from round 14).
//  LAYER 0: ROWS=64 per CTA (4m x 2n warps); LAYER 1: ROWS=32 (2m x 4n).
// Dynamic smem (bytes), total 103,424.
// ---------------------------------------------------------------------------
#define CPITCH 136
#define BPAD   72
#define CONV_SMEM_BYTES (17408 + 67584 + 18432)

template <int LAYER>
__global__ __launch_bounds__(256, 2) void k_conv_mma(
    const int*   __restrict__ nbr,   // random-edge srcs, nbr[8*dst + k]
    const float* __restrict__ b,     // [128]
    const float* __restrict__ bagg,  // [128]
    float*       __restrict__ dout)  // layer1 output
{
    constexpr int ROWS = (LAYER == 0) ? 64 : 32;
    constexpr int NWN  = (LAYER == 0) ? 2 : 4;
    constexpr int NWM  = 8 / NWN;
    constexpr int NJ   = 128 / (NWN * 8);

    extern __shared__ char smem[];
    __half* Sagg = (__half*)smem;                    // [<=64][CPITCH]
    __half* Wsm  = (__half*)(smem + 17408);          // [128][WPITCH]
    __half* B2   = (__half*)(smem + 84992);          // [128][BPAD]
    float* red    = (float*)(smem + 84992);          // epilogue only (L0)
    float* scales = (float*)(smem + 84992 + 512);    // (L0)

    const int tid  = threadIdx.x;
    const int lane = tid & 31;
    const int warp = tid >> 5;
    const int wm   = warp % NWM;
    const int wn   = warp / NWM;
    const int gID  = lane >> 2;
    const int qid  = lane & 3;
    const long long m0 = (long long)blockIdx.x * ROWS;
    const int mbase = wm * 16;
    const int nbase = wn * (NJ * 8);
    const int WOFF  = (LAYER == 0) ? OFF_W0 : OFF_W1;
    const int AOFF  = (LAYER == 0) ? OFF_WAGG0 : OFF_WAGG1;
    const __half* hsrc = (LAYER == 0) ? g_h0h : g_h1h;

    // ---- stage whole W [128x256] and Wagg chunk0 [128x64] ----
#pragma unroll
    for (int it = 0; it < 16; it++) {
        int g = tid + 256 * it;
        int n = g >> 5;
        int c = (g & 31) * 8;
        *(uint4*)&Wsm[n * WPITCH + c] = *(const uint4*)(g_w16 + WOFF + n * CONTC + c);
    }
#pragma unroll
    for (int it = 0; it < 4; it++) {
        int g = tid + 256 * it;
        int n = g >> 3;
        int c = (g & 7) * 8;
        *(uint4*)&B2[n * BPAD + c] = *(const uint4*)(g_w16 + AOFF + n * FEATC + c);
    }

    // ---- phase 1: gather-mean, 2 rows in flight per warp iteration ----
#pragma unroll
    for (int rp = 0; rp < ROWS / 16; rp++) {
        int rr0 = warp + rp * 16;
        int rr1 = rr0 + 8;
        long long d0 = m0 + rr0, d1 = m0 + rr1;
        int4 ea0 = *(const int4*)(nbr + d0 * 8);
        int4 eb0 = *(const int4*)(nbr + d0 * 8 + 4);
        int4 ea1 = *(const int4*)(nbr + d1 * 8);
        int4 eb1 = *(const int4*)(nbr + d1 * 8 + 4);
        int idx0[8] = {ea0.x, ea0.y, ea0.z, ea0.w, eb0.x, eb0.y, eb0.z, eb0.w};
        int idx1[8] = {ea1.x, ea1.y, ea1.z, ea1.w, eb1.x, eb1.y, eb1.z, eb1.w};
        uint2 u0[8], u1[8];
#pragma unroll
        for (int k = 0; k < 8; k++)
            u0[k] = *(const uint2*)(hsrc + (long long)idx0[k] * FEATC + lane * 4);
#pragma unroll
        for (int k = 0; k < 8; k++)
            u1[k] = *(const uint2*)(hsrc + (long long)idx1[k] * FEATC + lane * 4);

        float4 s0 = make_float4(0.f, 0.f, 0.f, 0.f);
        float4 s1 = make_float4(0.f, 0.f, 0.f, 0.f);
#pragma unroll
        for (int k = 0; k < 8; k++) {
            float2 f0 = __half22float2(*(__half2*)&u0[k].x);
            float2 f1 = __half22float2(*(__half2*)&u0[k].y);
            s0.x += f0.x; s0.y += f0.y; s0.z += f1.x; s0.w += f1.y;
            float2 g0 = __half22float2(*(__half2*)&u1[k].x);
            float2 g1 = __half22float2(*(__half2*)&u1[k].y);
            s1.x += g0.x; s1.y += g0.y; s1.z += g1.x; s1.w += g1.y;
        }
        if (LAYER == 1) {
            uint2 a1 = *(const uint2*)(g_h1h + d0 * FEATC + lane * 4);
            uint2 c1 = *(const uint2*)(g_h0h + d0 * FEATC + lane * 4);
            uint2 a2 = *(const uint2*)(g_h1h + d1 * FEATC + lane * 4);
            uint2 c2 = *(const uint2*)(g_h0h + d1 * FEATC + lane * 4);
            float2 p0 = __half22float2(*(__half2*)&a1.x), p1 = __half22float2(*(__half2*)&a1.y);
            float2 q0 = __half22float2(*(__half2*)&c1.x), q1 = __half22float2(*(__half2*)&c1.y);
            s0.x += p0.x - q0.x; s0.y += p0.y - q0.y;
            s0.z += p1.x - q1.x; s0.w += p1.y - q1.y;
            float2 r0 = __half22float2(*(__half2*)&a2.x), r1 = __half22float2(*(__half2*)&a2.y);
            float2 t0 = __half22float2(*(__half2*)&c2.x), t1 = __half22float2(*(__half2*)&c2.y);
            s1.x += r0.x - t0.x; s1.y += r0.y - t0.y;
            s1.z += r1.x - t1.x; s1.w += r1.y - t1.y;
        }
        s0.x *= 0.125f; s0.y *= 0.125f; s0.z *= 0.125f; s0.w *= 0.125f;
        s1.x *= 0.125f; s1.y *= 0.125f; s1.z *= 0.125f; s1.w *= 0.125f;
        uint2 o0, o1;
        *(__half2*)&o0.x = __floats2half2_rn(s0.x, s0.y);
        *(__half2*)&o0.y = __floats2half2_rn(s0.z, s0.w);
        *(__half2*)&o1.x = __floats2half2_rn(s1.x, s1.y);
        *(__half2*)&o1.y = __floats2half2_rn(s1.z, s1.w);
        *(uint2*)&Sagg[rr0 * CPITCH + lane * 4] = o0;
        *(uint2*)&Sagg[rr1 * CPITCH + lane * 4] = o1;
    }

    float acc1[NJ][4], acc2[NJ][4];
#pragma unroll
    for (int nj = 0; nj < NJ; nj++)
#pragma unroll
        for (int t = 0; t < 4; t++) { acc1[nj][t] = 0.f; acc2[nj][t] = 0.f; }

    __syncthreads();   // sync 1: Sagg + Wsm + B2(chunk0) ready

    // ---- kc = 0,1: acc1 += X @ W[:,0:128].T ----
#pragma unroll
    for (int kc = 0; kc < 2; kc++) {
#pragma unroll
        for (int s = 0; s < 4; s++) {
            uint32_t a[4];
            const __half* ab = g_h0h + (m0 + mbase + gID) * (long long)FEATC
                             + kc * 64 + s * 16 + qid * 2;
#pragma unroll
            for (int rr = 0; rr < 2; rr++)
#pragma unroll
                for (int kk = 0; kk < 2; kk++)
                    a[rr + kk * 2] = *(const uint32_t*)(ab + rr * 8 * FEATC + kk * 8);
            int cb = kc * 64 + s * 16 + qid * 2;
#pragma unroll
            for (int nj = 0; nj < NJ; nj++) {
                int n = nbase + nj * 8 + gID;
                uint32_t bb[2];
                bb[0] = *(const uint32_t*)&Wsm[n * WPITCH + cb];
                bb[1] = *(const uint32_t*)&Wsm[n * WPITCH + cb + 8];
                mma16816h(acc1[nj], a, bb);
            }
        }
    }

    // ---- kc = 2: Agg @ (W[:,128:192] and Wagg[:,0:64]) ----
#pragma unroll
    for (int s = 0; s < 4; s++) {
        uint32_t a[4];
        const __half* ab = Sagg + (mbase + gID) * CPITCH + s * 16 + qid * 2;
#pragma unroll
        for (int rr = 0; rr < 2; rr++)
#pragma unroll
            for (int kk = 0; kk < 2; kk++)
                a[rr + kk * 2] = *(const uint32_t*)(ab + rr * 8 * CPITCH + kk * 8);
        int cb = 128 + s * 16 + qid * 2;
        int cb2 = s * 16 + qid * 2;
#pragma unroll
        for (int nj = 0; nj < NJ; nj++) {
            int n = nbase + nj * 8 + gID;
            uint32_t bb[2], cc[2];
            bb[0] = *(const uint32_t*)&Wsm[n * WPITCH + cb];
            bb[1] = *(const uint32_t*)&Wsm[n * WPITCH + cb + 8];
            cc[0] = *(const uint32_t*)&B2[n * BPAD + cb2];
            cc[1] = *(const uint32_t*)&B2[n * BPAD + cb2 + 8];
            mma16816h(acc1[nj], a, bb);
            mma16816h(acc2[nj], a, cc);
        }
    }

    __syncthreads();   // sync 2: B2 chunk0 consumed
#pragma unroll
    for (int it = 0; it < 4; it++) {
        int g = tid + 256 * it;
        int n = g >> 3;
        int c = (g & 7) * 8;
        *(uint4*)&B2[n * BPAD + c] = *(const uint4*)(g_w16 + AOFF + n * FEATC + 64 + c);
    }
    __syncthreads();   // sync 3: B2 chunk1 ready

    // ---- kc = 3: Agg @ (W[:,192:256] and Wagg[:,64:128]) ----
#pragma unroll
    for (int s = 0; s < 4; s++) {
        uint32_t a[4];
        const __half* ab = Sagg + (mbase + gID) * CPITCH + 64 + s * 16 + qid * 2;
#pragma unroll
        for (int rr = 0; rr < 2; rr++)
#pragma unroll
            for (int kk = 0; kk < 2; kk++)
                a[rr + kk * 2] = *(const uint32_t*)(ab + rr * 8 * CPITCH + kk * 8);
        int cb = 192 + s * 16 + qid * 2;
        int cb2 = s * 16 + qid * 2;
#pragma unroll
        for (int nj = 0; nj < NJ; nj++) {
            int n = nbase + nj * 8 + gID;
            uint32_t bb[2], cc[2];
            bb[0] = *(const uint32_t*)&Wsm[n * WPITCH + cb];
            bb[1] = *(const uint32_t*)&Wsm[n * WPITCH + cb + 8];
            cc[0] = *(const uint32_t*)&B2[n * BPAD + cb2];
            cc[1] = *(const uint32_t*)&B2[n * BPAD + cb2 + 8];
            mma16816h(acc1[nj], a, bb);
            mma16816h(acc2[nj], a, cc);
        }
    }
    __syncthreads();   // sync 4: B2 region free for red/scales overlay

    // ---- epilogue ----
    float ss[2] = {0.f, 0.f};
#pragma unroll
    for (int rr = 0; rr < 2; rr++)
#pragma unroll
        for (int nj = 0; nj < NJ; nj++) {
            int c = nbase + nj * 8 + qid * 2;
#pragma unroll
            for (int k = 0; k < 2; k++) {
                float t1 = acc1[nj][rr * 2 + k] + b[c + k];
                float t2 = acc2[nj][rr * 2 + k] + bagg[c + k];
                if (LAYER == 0) { t1 = leaky01(t1); t2 = leaky01(t2); }
                float v = t1 + t2;
                acc1[nj][rr * 2 + k] = v;
                if (LAYER == 0) ss[rr] = fmaf(v, v, ss[rr]);
            }
        }

    if (LAYER == 0) {
#pragma unroll
        for (int rr = 0; rr < 2; rr++) {
            float v = ss[rr];
            v += __shfl_xor_sync(0xFFFFFFFF, v, 1);
            v += __shfl_xor_sync(0xFFFFFFFF, v, 2);
            ss[rr] = v;
        }
        if (qid == 0) {
#pragma unroll
            for (int rr = 0; rr < 2; rr++) {
                int rl = mbase + rr * 8 + gID;
                red[rl * 2 + wn] = ss[rr];
            }
        }
        __syncthreads();
        if (tid < 64) {
            float s = red[tid * 2] + red[tid * 2 + 1];
            scales[tid] = 1.0f / fmaxf(sqrtf(s), 1e-6f);
        }
        __syncthreads();
#pragma unroll
        for (int rr = 0; rr < 2; rr++) {
            int rl = mbase + rr * 8 + gID;
            float sc = scales[rl];
            __half* orow = g_h1h + (m0 + rl) * (long long)FEATC;
#pragma unroll
            for (int nj = 0; nj < NJ; nj++) {
                int c = nbase + nj * 8 + qid * 2;
                *(__half2*)(orow + c) = __floats2half2_rn(
                    acc1[nj][rr * 2 + 0] * sc, acc1[nj][rr * 2 + 1] * sc);
            }
        }
    } else {
#pragma unroll
        for (int rr = 0; rr < 2; rr++) {
            int rl = mbase + rr * 8 + gID;
            float* orow = dout + (m0 + rl) * (long long)FEATC;
#pragma unroll
            for (int nj = 0; nj < NJ; nj++) {
                int c = nbase + nj * 8 + qid * 2;
                float2 o;
                o.x = acc1[nj][rr * 2 + 0];
                o.y = acc1[nj][rr * 2 + 1];
                *(float2*)(orow + c) = o;
            }
        }
    }
}

// ---------------------------------------------------------------------------
// kernel_launch
// ---------------------------------------------------------------------------
extern "C" void kernel_launch(void* const* d_in, const int* in_sizes, int n_in,
                              void* d_out, int out_size)
{
    const float* node_emb = (const float*)d_in[0];
    const float* content0 = (const float*)d_in[1];
    const float* Wp    = (const float*)d_in[2];
    const float* bp    = (const float*)d_in[3];
    const float* W0    = (const float*)d_in[4];
    const float* b0    = (const float*)d_in[5];
    const float* Wagg0 = (const float*)d_in[6];
    const float* bagg0 = (const float*)d_in[7];
    const float* W1    = (const float*)d_in[8];
    const float* b1    = (const float*)d_in[9];
    const float* Wagg1 = (const float*)d_in[10];
    const float* bagg1 = (const float*)d_in[11];
    const int* parent0 = (const int*)d_in[12];
    const int* src0    = (const int*)d_in[13];
    const int* src1    = (const int*)d_in[15];
    float* out = (float*)d_out;

    cudaFuncSetAttribute(k_h0_mma, cudaFuncAttributeMaxDynamicSharedMemorySize, H0_SMEM_BYTES);
    cudaFuncSetAttribute(k_conv_mma<0>, cudaFuncAttributeMaxDynamicSharedMemorySize, CONV_SMEM_BYTES);
    cudaFuncSetAttribute(k_conv_mma<1>, cudaFuncAttributeMaxDynamicSharedMemorySize, CONV_SMEM_BYTES);

    k_mask_zero<<<(S0C / 4 + 255) / 256, 256>>>();
    k_mask_set<<<(8 * S1C + 255) / 256, 256>>>(src0 + S1C);
    k_prep<<<(W_TOTAL + 255) / 256, 256>>>(Wp, W0, Wagg0, W1, Wagg1);
    k_h0_mma<<<S0C / 128, 256, H0_SMEM_BYTES>>>(content0, bp, node_emb, parent0);
    k_conv_mma<0><<<S1C / 64, 256, CONV_SMEM_BYTES>>>(src0 + S1C, b0, bagg0, nullptr);
    k_conv_mma<1><<<S2C / 32, 256, CONV_SMEM_BYTES>>>(src1 + S2C, b1, bagg1, out);
}

// round 17
// speedup vs baseline: 1.8663x; 1.1094x over previous
#include <cuda_runtime.h>
#include <cuda_fp16.h>
#include <cstdint>

// ---------------------------------------------------------------------------
// GraphSAGE with sampling, GB300 (compute_103 virtual arch -> no tcgen05).
// Round 16 = round 15 + k-permutation in every k16 MMA step:
//  fragment k-pairs remapped {2q,2q+1},{2q+8,2q+9} -> {4q..4q+3} so
//  A loads widen (float2->float4 / 2x ldg.32->ldg.64) and B fragments load
//  as one LDS.64. Exact math (A and B agree on slot->k mapping).
//  Pitches 272/144/80 keep LDS.64 conflict-free (row stride = 8 mod 32 words).
// Env constraint: dynamic smem <= ~116 KB per CTA (conv uses 108,544 B).
// ---------------------------------------------------------------------------

#define FEATC 128
#define CONTC 256
#define S2C   8192
#define S1C   73728        /* S2*9 */
#define S0C   663552       /* S1*9 */

// weight pool offsets (elements)
#define OFF_WP    0
#define OFF_W0    32768
#define OFF_WAGG0 65536
#define OFF_W1    81920
#define OFF_WAGG1 114688
#define W_TOTAL   131072

__device__ __half g_h0h[(long long)S0C * FEATC];   // 169.9 MB scratch
__device__ __half g_h1h[(long long)S1C * FEATC];   // 18.9 MB scratch
__device__ __half g_w16[W_TOTAL];                  // fp16 weights (all 5)
__device__ unsigned char g_mask[S0C];              // h0-row liveness

static __device__ __forceinline__ float leaky01(float x) {
    return x < 0.0f ? 0.1f * x : x;
}
static __device__ __forceinline__ uint32_t h2u(__half2 h) {
    return *reinterpret_cast<uint32_t*>(&h);
}

// mma.sync m16n8k16 row.col f32.f16.f16.f32, accumulate in place
static __device__ __forceinline__ void mma16816h(
    float* c, const uint32_t* a, const uint32_t* b)
{
    asm volatile(
        "mma.sync.aligned.m16n8k16.row.col.f32.f16.f16.f32 "
        "{%0,%1,%2,%3}, {%4,%5,%6,%7}, {%8,%9}, {%0,%1,%2,%3};"
        : "+f"(c[0]), "+f"(c[1]), "+f"(c[2]), "+f"(c[3])
        : "r"(a[0]), "r"(a[1]), "r"(a[2]), "r"(a[3]),
          "r"(b[0]), "r"(b[1]));
}

// ---------------------------------------------------------------------------
// mask kernels: zero, then scatter 1s at random-edge targets of src0.
// ---------------------------------------------------------------------------
__global__ void k_mask_zero()
{
    int i = blockIdx.x * blockDim.x + threadIdx.x;
    if (i < S0C / 4) ((uint32_t*)g_mask)[i] = 0u;
}
__global__ void k_mask_set(const int* __restrict__ rand_src)   // 8*S1C entries
{
    int i = blockIdx.x * blockDim.x + threadIdx.x;
    if (i < 8 * S1C) g_mask[rand_src[i]] = 1;
}

// ---------------------------------------------------------------------------
// k_prep: fp16 conversion of all weight matrices.
// ---------------------------------------------------------------------------
__global__ void k_prep(const float* __restrict__ Wp, const float* __restrict__ W0,
                       const float* __restrict__ Wagg0, const float* __restrict__ W1,
                       const float* __restrict__ Wagg1)
{
    int i = blockIdx.x * blockDim.x + threadIdx.x;
    if (i >= W_TOTAL) return;
    float v;
    if      (i < OFF_W0)    v = Wp[i - OFF_WP];
    else if (i < OFF_WAGG0) v = W0[i - OFF_W0];
    else if (i < OFF_W1)    v = Wagg0[i - OFF_WAGG0];
    else if (i < OFF_WAGG1) v = W1[i - OFF_W1];
    else                    v = Wagg1[i - OFF_WAGG1];
    g_w16[i] = __float2half_rn(v);
}

// ---------------------------------------------------------------------------
// k_h0_mma: fp16 GEMM, CTA 128x128, whole Wp in smem, one sync.
// k-permuted fragments: A rows load float4 (cols 4q..4q+3), B one LDS.64.
// Dead rows (mask==0, row>=S1) skip content loads, node_emb gather, store.
// ---------------------------------------------------------------------------
#define WPITCH 272
#define H0_SMEM_BYTES (128 * WPITCH * 2)   /* 69,632 B */

__global__ __launch_bounds__(256, 2) void k_h0_mma(
    const float* __restrict__ content,   // [S0,256]
    const float* __restrict__ bp,        // [128]
    const float* __restrict__ node_emb,  // [N+1,128]
    const int*   __restrict__ parent)    // [S0]
{
    extern __shared__ __half Ws[];       // [128][WPITCH]

    const int tid  = threadIdx.x;
    const int lane = tid & 31;
    const int warp = tid >> 5;
    const int gID  = lane >> 2;
    const int qid  = lane & 3;
    const long long m0 = (long long)blockIdx.x * 128;
    const int mbase = warp * 16;

#pragma unroll
    for (int it = 0; it < 16; it++) {
        int g = tid + 256 * it;
        int n = g >> 5;
        int c = (g & 31) * 8;
        *(uint4*)&Ws[n * WPITCH + c] = *(const uint4*)(g_w16 + OFF_WP + n * CONTC + c);
    }

    // liveness + parent for this thread's two output rows
    const long long r0e = m0 + mbase + gID;
    const long long r1e = r0e + 8;
    const bool use0 = (r0e < S1C) || (g_mask[r0e] != 0);
    const bool use1 = (r1e < S1C) || (g_mask[r1e] != 0);
    const long long p0 = use0 ? (long long)parent[r0e] + 1 : 0;
    const long long p1 = use1 ? (long long)parent[r1e] + 1 : 0;

    float acc[16][4];
#pragma unroll
    for (int nj = 0; nj < 16; nj++)
#pragma unroll
        for (int t = 0; t < 4; t++) acc[nj][t] = 0.0f;

    // prefetch A for k-step 0 (float4, cols 4q..4q+3; predicated)
    const float* abase = content + (m0 + mbase + gID) * (long long)CONTC + qid * 4;
    const float4 zz4 = make_float4(0.f, 0.f, 0.f, 0.f);
    float4 v0c, v1c, v0n, v1n;
    v0c = use0 ? *(const float4*)(abase) : zz4;
    v1c = use1 ? *(const float4*)(abase + 8 * CONTC) : zz4;

    __syncthreads();

#pragma unroll
    for (int st = 0; st < 16; st++) {
        if (st < 15) {
            v0n = use0 ? *(const float4*)(abase + (st + 1) * 16) : zz4;
            v1n = use1 ? *(const float4*)(abase + (st + 1) * 16 + 8 * CONTC) : zz4;
        }
        uint32_t a[4];
        a[0] = h2u(__floats2half2_rn(v0c.x, v0c.y));
        a[1] = h2u(__floats2half2_rn(v1c.x, v1c.y));
        a[2] = h2u(__floats2half2_rn(v0c.z, v0c.w));
        a[3] = h2u(__floats2half2_rn(v1c.z, v1c.w));
        int cb = st * 16 + qid * 4;
#pragma unroll
        for (int nj = 0; nj < 16; nj++) {
            int n = nj * 8 + gID;
            uint2 b64 = *(const uint2*)&Ws[n * WPITCH + cb];
            uint32_t b[2] = {b64.x, b64.y};
            mma16816h(acc[nj], a, b);
        }
        if (st < 15) { v0c = v0n; v1c = v1n; }
    }

    // epilogue: bias + leaky + node_emb gather -> g_h0h (live rows only)
#pragma unroll
    for (int rr = 0; rr < 2; rr++) {
        const bool u = (rr == 0) ? use0 : use1;
        if (!u) continue;
        long long r = (rr == 0) ? r0e : r1e;
        long long p = (rr == 0) ? p0 : p1;
        const float* ne = node_emb + p * FEATC;
        __half* orow = g_h0h + r * FEATC;
#pragma unroll
        for (int nj = 0; nj < 16; nj++) {
            int c = nj * 8 + qid * 2;
            float2 bv = *(const float2*)(bp + c);
            float2 nv = *(const float2*)(ne + c);
            float ox = leaky01(acc[nj][rr * 2 + 0] + bv.x) + nv.x;
            float oy = leaky01(acc[nj][rr * 2 + 1] + bv.y) + nv.y;
            *(__half2*)(orow + c) = __floats2half2_rn(ox, oy);
        }
    }
}

// ---------------------------------------------------------------------------
// k_conv_mma<LAYER>: fused gather + GEMM, k-permuted fragments.
//  LAYER 0: ROWS=64 per CTA (4m x 2n warps); LAYER 1: ROWS=32 (2m x 4n).
// Dynamic smem (bytes), total 108,544:
//   [0, 18432)          Sagg  half[64][144]
//   [18432, +69632)     Wsm   half[128][272]
//   [88064, +20480)     B2    half[128][80]   (red/scales overlay in epilogue)
// ---------------------------------------------------------------------------
#define CPITCH 144
#define BPAD   80
#define CONV_SMEM_BYTES (18432 + 69632 + 20480)

template <int LAYER>
__global__ __launch_bounds__(256, 2) void k_conv_mma(
    const int*   __restrict__ nbr,   // random-edge srcs, nbr[8*dst + k]
    const float* __restrict__ b,     // [128]
    const float* __restrict__ bagg,  // [128]
    float*       __restrict__ dout)  // layer1 output
{
    constexpr int ROWS = (LAYER == 0) ? 64 : 32;
    constexpr int NWN  = (LAYER == 0) ? 2 : 4;
    constexpr int NWM  = 8 / NWN;
    constexpr int NJ   = 128 / (NWN * 8);

    extern __shared__ char smem[];
    __half* Sagg = (__half*)smem;                    // [<=64][CPITCH]
    __half* Wsm  = (__half*)(smem + 18432);          // [128][WPITCH]
    __half* B2   = (__half*)(smem + 88064);          // [128][BPAD]
    float* red    = (float*)(smem + 88064);          // epilogue only (L0)
    float* scales = (float*)(smem + 88064 + 512);    // (L0)

    const int tid  = threadIdx.x;
    const int lane = tid & 31;
    const int warp = tid >> 5;
    const int wm   = warp % NWM;
    const int wn   = warp / NWM;
    const int gID  = lane >> 2;
    const int qid  = lane & 3;
    const long long m0 = (long long)blockIdx.x * ROWS;
    const int mbase = wm * 16;
    const int nbase = wn * (NJ * 8);
    const int WOFF  = (LAYER == 0) ? OFF_W0 : OFF_W1;
    const int AOFF  = (LAYER == 0) ? OFF_WAGG0 : OFF_WAGG1;
    const __half* hsrc = (LAYER == 0) ? g_h0h : g_h1h;

    // ---- stage whole W [128x256] and Wagg chunk0 [128x64] ----
#pragma unroll
    for (int it = 0; it < 16; it++) {
        int g = tid + 256 * it;
        int n = g >> 5;
        int c = (g & 31) * 8;
        *(uint4*)&Wsm[n * WPITCH + c] = *(const uint4*)(g_w16 + WOFF + n * CONTC + c);
    }
#pragma unroll
    for (int it = 0; it < 4; it++) {
        int g = tid + 256 * it;
        int n = g >> 3;
        int c = (g & 7) * 8;
        *(uint4*)&B2[n * BPAD + c] = *(const uint4*)(g_w16 + AOFF + n * FEATC + c);
    }

    // ---- phase 1: gather-mean, 2 rows in flight per warp iteration ----
#pragma unroll
    for (int rp = 0; rp < ROWS / 16; rp++) {
        int rr0 = warp + rp * 16;
        int rr1 = rr0 + 8;
        long long d0 = m0 + rr0, d1 = m0 + rr1;
        int4 ea0 = *(const int4*)(nbr + d0 * 8);
        int4 eb0 = *(const int4*)(nbr + d0 * 8 + 4);
        int4 ea1 = *(const int4*)(nbr + d1 * 8);
        int4 eb1 = *(const int4*)(nbr + d1 * 8 + 4);
        int idx0[8] = {ea0.x, ea0.y, ea0.z, ea0.w, eb0.x, eb0.y, eb0.z, eb0.w};
        int idx1[8] = {ea1.x, ea1.y, ea1.z, ea1.w, eb1.x, eb1.y, eb1.z, eb1.w};
        uint2 u0[8], u1[8];
#pragma unroll
        for (int k = 0; k < 8; k++)
            u0[k] = *(const uint2*)(hsrc + (long long)idx0[k] * FEATC + lane * 4);
#pragma unroll
        for (int k = 0; k < 8; k++)
            u1[k] = *(const uint2*)(hsrc + (long long)idx1[k] * FEATC + lane * 4);

        float4 s0 = make_float4(0.f, 0.f, 0.f, 0.f);
        float4 s1 = make_float4(0.f, 0.f, 0.f, 0.f);
#pragma unroll
        for (int k = 0; k < 8; k++) {
            float2 f0 = __half22float2(*(__half2*)&u0[k].x);
            float2 f1 = __half22float2(*(__half2*)&u0[k].y);
            s0.x += f0.x; s0.y += f0.y; s0.z += f1.x; s0.w += f1.y;
            float2 g0 = __half22float2(*(__half2*)&u1[k].x);
            float2 g1 = __half22float2(*(__half2*)&u1[k].y);
            s1.x += g0.x; s1.y += g0.y; s1.z += g1.x; s1.w += g1.y;
        }
        if (LAYER == 1) {
            uint2 a1 = *(const uint2*)(g_h1h + d0 * FEATC + lane * 4);
            uint2 c1 = *(const uint2*)(g_h0h + d0 * FEATC + lane * 4);
            uint2 a2 = *(const uint2*)(g_h1h + d1 * FEATC + lane * 4);
            uint2 c2 = *(const uint2*)(g_h0h + d1 * FEATC + lane * 4);
            float2 p0 = __half22float2(*(__half2*)&a1.x), p1 = __half22float2(*(__half2*)&a1.y);
            float2 q0 = __half22float2(*(__half2*)&c1.x), q1 = __half22float2(*(__half2*)&c1.y);
            s0.x += p0.x - q0.x; s0.y += p0.y - q0.y;
            s0.z += p1.x - q1.x; s0.w += p1.y - q1.y;
            float2 r0 = __half22float2(*(__half2*)&a2.x), r1 = __half22float2(*(__half2*)&a2.y);
            float2 t0 = __half22float2(*(__half2*)&c2.x), t1 = __half22float2(*(__half2*)&c2.y);
            s1.x += r0.x - t0.x; s1.y += r0.y - t0.y;
            s1.z += r1.x - t1.x; s1.w += r1.y - t1.y;
        }
        s0.x *= 0.125f; s0.y *= 0.125f; s0.z *= 0.125f; s0.w *= 0.125f;
        s1.x *= 0.125f; s1.y *= 0.125f; s1.z *= 0.125f; s1.w *= 0.125f;
        uint2 o0, o1;
        *(__half2*)&o0.x = __floats2half2_rn(s0.x, s0.y);
        *(__half2*)&o0.y = __floats2half2_rn(s0.z, s0.w);
        *(__half2*)&o1.x = __floats2half2_rn(s1.x, s1.y);
        *(__half2*)&o1.y = __floats2half2_rn(s1.z, s1.w);
        *(uint2*)&Sagg[rr0 * CPITCH + lane * 4] = o0;
        *(uint2*)&Sagg[rr1 * CPITCH + lane * 4] = o1;
    }

    float acc1[NJ][4], acc2[NJ][4];
#pragma unroll
    for (int nj = 0; nj < NJ; nj++)
#pragma unroll
        for (int t = 0; t < 4; t++) { acc1[nj][t] = 0.f; acc2[nj][t] = 0.f; }

    __syncthreads();   // sync 1: Sagg + Wsm + B2(chunk0) ready

    // ---- kc = 0,1: acc1 += X @ W[:,0:128].T ----
#pragma unroll
    for (int kc = 0; kc < 2; kc++) {
#pragma unroll
        for (int s = 0; s < 4; s++) {
            int ko = kc * 64 + s * 16 + qid * 4;
            const __half* ab = g_h0h + (m0 + mbase + gID) * (long long)FEATC + ko;
            uint2 av0 = *(const uint2*)(ab);
            uint2 av1 = *(const uint2*)(ab + 8 * FEATC);
            uint32_t a[4] = {av0.x, av1.x, av0.y, av1.y};
            int cb = ko;
#pragma unroll
            for (int nj = 0; nj < NJ; nj++) {
                int n = nbase + nj * 8 + gID;
                uint2 b64 = *(const uint2*)&Wsm[n * WPITCH + cb];
                uint32_t bb[2] = {b64.x, b64.y};
                mma16816h(acc1[nj], a, bb);
            }
        }
    }

    // ---- kc = 2: Agg @ (W[:,128:192] and Wagg[:,0:64]) ----
#pragma unroll
    for (int s = 0; s < 4; s++) {
        int ko = s * 16 + qid * 4;
        const __half* ab = Sagg + (mbase + gID) * CPITCH + ko;
        uint2 av0 = *(const uint2*)(ab);
        uint2 av1 = *(const uint2*)(ab + 8 * CPITCH);
        uint32_t a[4] = {av0.x, av1.x, av0.y, av1.y};
#pragma unroll
        for (int nj = 0; nj < NJ; nj++) {
            int n = nbase + nj * 8 + gID;
            uint2 b64 = *(const uint2*)&Wsm[n * WPITCH + 128 + ko];
            uint2 c64 = *(const uint2*)&B2[n * BPAD + ko];
            uint32_t bb[2] = {b64.x, b64.y};
            uint32_t cc[2] = {c64.x, c64.y};
            mma16816h(acc1[nj], a, bb);
            mma16816h(acc2[nj], a, cc);
        }
    }

    __syncthreads();   // sync 2: B2 chunk0 consumed
#pragma unroll
    for (int it = 0; it < 4; it++) {
        int g = tid + 256 * it;
        int n = g >> 3;
        int c = (g & 7) * 8;
        *(uint4*)&B2[n * BPAD + c] = *(const uint4*)(g_w16 + AOFF + n * FEATC + 64 + c);
    }
    __syncthreads();   // sync 3: B2 chunk1 ready

    // ---- kc = 3: Agg @ (W[:,192:256] and Wagg[:,64:128]) ----
#pragma unroll
    for (int s = 0; s < 4; s++) {
        int ko = s * 16 + qid * 4;
        const __half* ab = Sagg + (mbase + gID) * CPITCH + 64 + ko;
        uint2 av0 = *(const uint2*)(ab);
        uint2 av1 = *(const uint2*)(ab + 8 * CPITCH);
        uint32_t a[4] = {av0.x, av1.x, av0.y, av1.y};
#pragma unroll
        for (int nj = 0; nj < NJ; nj++) {
            int n = nbase + nj * 8 + gID;
            uint2 b64 = *(const uint2*)&Wsm[n * WPITCH + 192 + ko];
            uint2 c64 = *(const uint2*)&B2[n * BPAD + ko];
            uint32_t bb[2] = {b64.x, b64.y};
            uint32_t cc[2] = {c64.x, c64.y};
            mma16816h(acc1[nj], a, bb);
            mma16816h(acc2[nj], a, cc);
        }
    }
    __syncthreads();   // sync 4: B2 region free for red/scales overlay

    // ---- epilogue ----
    float ss[2] = {0.f, 0.f};
#pragma unroll
    for (int rr = 0; rr < 2; rr++)
#pragma unroll
        for (int nj = 0; nj < NJ; nj++) {
            int c = nbase + nj * 8 + qid * 2;
#pragma unroll
            for (int k = 0; k < 2; k++) {
                float t1 = acc1[nj][rr * 2 + k] + b[c + k];
                float t2 = acc2[nj][rr * 2 + k] + bagg[c + k];
                if (LAYER == 0) { t1 = leaky01(t1); t2 = leaky01(t2); }
                float v = t1 + t2;
                acc1[nj][rr * 2 + k] = v;
                if (LAYER == 0) ss[rr] = fmaf(v, v, ss[rr]);
            }
        }

    if (LAYER == 0) {
#pragma unroll
        for (int rr = 0; rr < 2; rr++) {
            float v = ss[rr];
            v += __shfl_xor_sync(0xFFFFFFFF, v, 1);
            v += __shfl_xor_sync(0xFFFFFFFF, v, 2);
            ss[rr] = v;
        }
        if (qid == 0) {
#pragma unroll
            for (int rr = 0; rr < 2; rr++) {
                int rl = mbase + rr * 8 + gID;
                red[rl * 2 + wn] = ss[rr];
            }
        }
        __syncthreads();
        if (tid < 64) {
            float s = red[tid * 2] + red[tid * 2 + 1];
            scales[tid] = 1.0f / fmaxf(sqrtf(s), 1e-6f);
        }
        __syncthreads();
#pragma unroll
        for (int rr = 0; rr < 2; rr++) {
            int rl = mbase + rr * 8 + gID;
            float sc = scales[rl];
            __half* orow = g_h1h + (m0 + rl) * (long long)FEATC;
#pragma unroll
            for (int nj = 0; nj < NJ; nj++) {
                int c = nbase + nj * 8 + qid * 2;
                *(__half2*)(orow + c) = __floats2half2_rn(
                    acc1[nj][rr * 2 + 0] * sc, acc1[nj][rr * 2 + 1] * sc);
            }
        }
    } else {
#pragma unroll
        for (int rr = 0; rr < 2; rr++) {
            int rl = mbase + rr * 8 + gID;
            float* orow = dout + (m0 + rl) * (long long)FEATC;
#pragma unroll
            for (int nj = 0; nj < NJ; nj++) {
                int c = nbase + nj * 8 + qid * 2;
                float2 o;
                o.x = acc1[nj][rr * 2 + 0];
                o.y = acc1[nj][rr * 2 + 1];
                *(float2*)(orow + c) = o;
            }
        }
    }
}

// ---------------------------------------------------------------------------
// kernel_launch
// ---------------------------------------------------------------------------
extern "C" void kernel_launch(void* const* d_in, const int* in_sizes, int n_in,
                              void* d_out, int out_size)
{
    const float* node_emb = (const float*)d_in[0];
    const float* content0 = (const float*)d_in[1];
    const float* Wp    = (const float*)d_in[2];
    const float* bp    = (const float*)d_in[3];
    const float* W0    = (const float*)d_in[4];
    const float* b0    = (const float*)d_in[5];
    const float* Wagg0 = (const float*)d_in[6];
    const float* bagg0 = (const float*)d_in[7];
    const float* W1    = (const float*)d_in[8];
    const float* b1    = (const float*)d_in[9];
    const float* Wagg1 = (const float*)d_in[10];
    const float* bagg1 = (const float*)d_in[11];
    const int* parent0 = (const int*)d_in[12];
    const int* src0    = (const int*)d_in[13];
    const int* src1    = (const int*)d_in[15];
    float* out = (float*)d_out;

    cudaFuncSetAttribute(k_h0_mma, cudaFuncAttributeMaxDynamicSharedMemorySize, H0_SMEM_BYTES);
    cudaFuncSetAttribute(k_conv_mma<0>, cudaFuncAttributeMaxDynamicSharedMemorySize, CONV_SMEM_BYTES);
    cudaFuncSetAttribute(k_conv_mma<1>, cudaFuncAttributeMaxDynamicSharedMemorySize, CONV_SMEM_BYTES);

    k_mask_zero<<<(S0C / 4 + 255) / 256, 256>>>();
    k_mask_set<<<(8 * S1C + 255) / 256, 256>>>(src0 + S1C);
    k_prep<<<(W_TOTAL + 255) / 256, 256>>>(Wp, W0, Wagg0, W1, Wagg1);
    k_h0_mma<<<S0C / 128, 256, H0_SMEM_BYTES>>>(content0, bp, node_emb, parent0);
    k_conv_mma<0><<<S1C / 64, 256, CONV_SMEM_BYTES>>>(src0 + S1C, b0, bagg0, nullptr);
    k_conv_mma<1><<<S2C / 32, 256, CONV_SMEM_BYTES>>>(src1 + S2C, b1, bagg1, out);
}